// round 12
// baseline (speedup 1.0000x reference)
#include <cuda_runtime.h>
#include <cuda_bf16.h>
#include <cstdint>
#include <math.h>

// Problem constants
#define B   16
#define L   512
#define D   512
#define NH  8
#define HD  64
#define T   17
#define CYC 2
#define BL  (B * L)   // 8192
#define DD  (D * D)

// Weight slot order (transposed buffer): 0 sat_q, 1 sat_k, 2 sat_v,
// 3 rel_k, 4 rel_v, 5 sat_o, 6 rel_q, 7 rel_o
// ---------------------------------------------------------------------------
// Scratch (device globals)
// ---------------------------------------------------------------------------
__device__ float g_e[BL * D];
__device__ float g_h[BL * D];
__device__ float g_s[B * D];
__device__ float g_qkv[BL * 1536];    // cyc1: q | k | v
__device__ float g_qkeve[BL * 1536];  // cyc0: q | ke | ve
__device__ float g_big[BL * 2560];    // cyc0 h-proj: q | k | v | kr | vr
__device__ float g_a[BL * D];
__device__ float g_ks[B * D];
__device__ float g_vs[B * D];
__device__ float g_qsr[B * D];
__device__ float g_ksr[B * D];
__device__ float g_vsr[B * D];
__device__ float g_ctxs[B * D];
__device__ float g_r[B * D];
__device__ float g_bias[8 * D];
__device__ float g_part[5 * 8 * 16 * 512];   // small-gemm K-split partials

// bf16 split buffers (16B aligned for cp.async 16)
__device__ __align__(16) __nv_bfloat16 g_ehi[BL * D];
__device__ __align__(16) __nv_bfloat16 g_elo[BL * D];
__device__ __align__(16) __nv_bfloat16 g_hhi[BL * D];
__device__ __align__(16) __nv_bfloat16 g_hlo[BL * D];
__device__ __align__(16) __nv_bfloat16 g_cthi[BL * D];
__device__ __align__(16) __nv_bfloat16 g_ctlo[BL * D];
__device__ __align__(16) __nv_bfloat16 g_whi[8 * DD];   // transposed [N][K]
__device__ __align__(16) __nv_bfloat16 g_wlo[8 * DD];

struct Ptr8 { const float* p[8]; };
struct SJobs { const float* W[5]; const float* bias[5]; float* C[5]; };

// ---------------------------------------------------------------------------
// Embedding: e fp32 + split bf16
// ---------------------------------------------------------------------------
__global__ void embed_split(const int* __restrict__ tokens,
                            const float* __restrict__ emb,
                            float* __restrict__ e,
                            __nv_bfloat16* __restrict__ hi,
                            __nv_bfloat16* __restrict__ lo) {
    int idx = blockIdx.x * 256 + threadIdx.x;
    int row = idx / D;
    int d   = idx - row * D;
    float v = emb[tokens[row] * D + d];
    e[idx] = v;
    __nv_bfloat16 hv = __float2bfloat16_rn(v);
    hi[idx] = hv;
    lo[idx] = __float2bfloat16_rn(v - __bfloat162float(hv));
}

// s[b,d] = mean_l e[b,l,d]
__global__ void smean_kernel(const float* __restrict__ e, float* __restrict__ s) {
    __shared__ float red[256];
    int b     = blockIdx.x >> 3;
    int dbase = (blockIdx.x & 7) * 64;
    int tid   = threadIdx.x;
    int d     = dbase + (tid & 63);
    int grp   = tid >> 6;
    const float* p = e + ((b << 9) + grp * 128) * D + d;
    float acc = 0.f;
    #pragma unroll 8
    for (int l = 0; l < 128; l++) acc += p[l * D];
    red[tid] = acc;
    __syncthreads();
    if (tid < 128) red[tid] += red[tid + 128];
    __syncthreads();
    if (tid < 64)
        s[b * D + d] = (red[tid] + red[tid + 64]) * (1.f / (float)L);
}

// ---------------------------------------------------------------------------
// Weight prep: split + transpose all 8 weights; concat biases
// ---------------------------------------------------------------------------
__global__ void wsplit_all(Ptr8 W, __nv_bfloat16* __restrict__ hi,
                           __nv_bfloat16* __restrict__ lo) {
    __shared__ float t[32][33];
    const float* Wsrc = W.p[blockIdx.z];
    __nv_bfloat16* hz = hi + blockIdx.z * DD;
    __nv_bfloat16* lz = lo + blockIdx.z * DD;
    int bx = blockIdx.x, by = blockIdx.y;
    int x = threadIdx.x, y = threadIdx.y;
    #pragma unroll
    for (int j = 0; j < 32; j += 8)
        t[y + j][x] = Wsrc[(by * 32 + y + j) * 512 + bx * 32 + x];
    __syncthreads();
    #pragma unroll
    for (int j = 0; j < 32; j += 8) {
        float v = t[x][y + j];
        int n = bx * 32 + y + j;
        int k = by * 32 + x;
        __nv_bfloat16 hv = __float2bfloat16_rn(v);
        hz[n * 512 + k] = hv;
        lz[n * 512 + k] = __float2bfloat16_rn(v - __bfloat162float(hv));
    }
}

__global__ void biascat(Ptr8 bsrc, float* __restrict__ dst) {
    int i = blockIdx.x * 256 + threadIdx.x;
    dst[i] = bsrc.p[i >> 9][i & 511];
}

// ---------------------------------------------------------------------------
// Tensor-core GEMM: C[8192,N] = A[8192,512] @ Wt[N,512]^T + bias
// 3-term bf16 split; ldmatrix; 128x128x32 tiles, 2-stage cp.async,
// single sync per K-iter. (Schedule at measured legacy-HMMA ceiling.)
// ---------------------------------------------------------------------------
#define SMEM_STAGE 20480
#define SMEM_BYTES (2 * SMEM_STAGE * 2)

__device__ __forceinline__ void mma16816(float* d, const uint32_t* a,
                                         const uint32_t* b) {
    asm volatile("mma.sync.aligned.m16n8k16.row.col.f32.bf16.bf16.f32 "
                 "{%0,%1,%2,%3}, {%4,%5,%6,%7}, {%8,%9}, {%0,%1,%2,%3};"
                 : "+f"(d[0]), "+f"(d[1]), "+f"(d[2]), "+f"(d[3])
                 : "r"(a[0]), "r"(a[1]), "r"(a[2]), "r"(a[3]),
                   "r"(b[0]), "r"(b[1]));
}

__device__ __forceinline__ void ldsm_x4(uint32_t* r, uint32_t a) {
    asm volatile("ldmatrix.sync.aligned.m8n8.x4.shared.b16 {%0,%1,%2,%3}, [%4];"
                 : "=r"(r[0]), "=r"(r[1]), "=r"(r[2]), "=r"(r[3]) : "r"(a));
}

__global__ void __launch_bounds__(256, 2)
mma_gemm(const __nv_bfloat16* __restrict__ Ahi, const __nv_bfloat16* __restrict__ Alo,
         const __nv_bfloat16* __restrict__ Whi, const __nv_bfloat16* __restrict__ Wlo,
         const float* __restrict__ bias, float* __restrict__ C, int ldc) {
    extern __shared__ __nv_bfloat16 sm[];
    const int tid  = threadIdx.x;
    const int lane = tid & 31;
    const int warp = tid >> 5;
    const int wm = warp >> 2;
    const int wn = warp & 3;
    const int m0 = blockIdx.y * 128;
    const int n0 = blockIdx.x * 128;

    float acc[4][4][4];
    #pragma unroll
    for (int i = 0; i < 4; i++)
        #pragma unroll
        for (int j = 0; j < 4; j++)
            #pragma unroll
            for (int t = 0; t < 4; t++) acc[i][j][t] = 0.f;

    uint32_t smbase = (uint32_t)__cvta_generic_to_shared(sm);

    auto load_stage = [&](int s, int k0) {
        uint32_t base = smbase + (uint32_t)(s * SMEM_STAGE * 2);
        #pragma unroll
        for (int i = 0; i < 2; i++) {
            int id  = tid + i * 256;
            int row = id >> 2;
            int qc  = (id & 3) << 3;
            uint32_t so = base + (uint32_t)((row * 40 + qc) * 2);
            const __nv_bfloat16* ga = Ahi + (m0 + row) * 512 + k0 + qc;
            const __nv_bfloat16* gb = Alo + (m0 + row) * 512 + k0 + qc;
            const __nv_bfloat16* gc = Whi + (n0 + row) * 512 + k0 + qc;
            const __nv_bfloat16* gd = Wlo + (n0 + row) * 512 + k0 + qc;
            asm volatile("cp.async.cg.shared.global [%0], [%1], 16;" :: "r"(so),           "l"(ga));
            asm volatile("cp.async.cg.shared.global [%0], [%1], 16;" :: "r"(so + 10240u), "l"(gb));
            asm volatile("cp.async.cg.shared.global [%0], [%1], 16;" :: "r"(so + 20480u), "l"(gc));
            asm volatile("cp.async.cg.shared.global [%0], [%1], 16;" :: "r"(so + 30720u), "l"(gd));
        }
    };

    load_stage(0, 0);
    asm volatile("cp.async.commit_group;");

    const int lrow  = lane & 15;
    const int lkoff = (lane >> 4) << 3;

    #pragma unroll 1
    for (int it = 0; it < 16; it++) {
        asm volatile("cp.async.wait_group 0;");
        __syncthreads();
        if (it < 15) {
            load_stage((it + 1) & 1, (it + 1) * 32);
            asm volatile("cp.async.commit_group;");
        }

        uint32_t st = smbase + (uint32_t)((it & 1) * SMEM_STAGE * 2);

        #pragma unroll
        for (int ks = 0; ks < 2; ks++) {
            int col = ks * 16 + lkoff;
            uint32_t bh[4][2], bl[4][2];
            #pragma unroll
            for (int ntp = 0; ntp < 2; ntp++) {
                int n = wn * 32 + ntp * 16 + lrow;
                uint32_t adr = st + 20480u + (uint32_t)((n * 40 + col) * 2);
                uint32_t t4[4];
                ldsm_x4(t4, adr);
                bh[ntp * 2 + 0][0] = t4[0]; bh[ntp * 2 + 0][1] = t4[2];
                bh[ntp * 2 + 1][0] = t4[1]; bh[ntp * 2 + 1][1] = t4[3];
                ldsm_x4(t4, adr + 10240u);
                bl[ntp * 2 + 0][0] = t4[0]; bl[ntp * 2 + 0][1] = t4[2];
                bl[ntp * 2 + 1][0] = t4[1]; bl[ntp * 2 + 1][1] = t4[3];
            }
            #pragma unroll
            for (int mt = 0; mt < 4; mt++) {
                int row = wm * 64 + mt * 16 + lrow;
                uint32_t adr = st + (uint32_t)((row * 40 + col) * 2);
                uint32_t ah[4], al[4];
                ldsm_x4(ah, adr);
                ldsm_x4(al, adr + 10240u);
                #pragma unroll
                for (int nt = 0; nt < 4; nt++) {
                    mma16816(acc[mt][nt], ah, bh[nt]);
                    mma16816(acc[mt][nt], ah, bl[nt]);
                    mma16816(acc[mt][nt], al, bh[nt]);
                }
            }
        }
    }

    const int r = lane >> 2;
    const int c = (lane & 3) << 1;
    #pragma unroll
    for (int mt = 0; mt < 4; mt++) {
        #pragma unroll
        for (int nt = 0; nt < 4; nt++) {
            int row = m0 + wm * 64 + mt * 16 + r;
            int col = n0 + wn * 32 + nt * 8 + c;
            float b0 = bias[col], b1 = bias[col + 1];
            float2 v0 = make_float2(acc[mt][nt][0] + b0, acc[mt][nt][1] + b1);
            float2 v1 = make_float2(acc[mt][nt][2] + b0, acc[mt][nt][3] + b1);
            *(float2*)(C + (size_t)row * ldc + col)       = v0;
            *(float2*)(C + (size_t)(row + 8) * ldc + col) = v1;
        }
    }
}

// ---------------------------------------------------------------------------
// Small GEMM, K-split 2-phase (deterministic); up to 5 jobs per launch
// ---------------------------------------------------------------------------
__global__ void __launch_bounds__(256)
sgemm16_part(const float* __restrict__ A, SJobs jobs, float* __restrict__ part) {
    __shared__ float As[16][64];
    int kc  = blockIdx.x;
    int job = blockIdx.y;
    int tid = threadIdx.x;
    for (int i = tid; i < 16 * 64; i += 256) {
        int r = i >> 6, kk = i & 63;
        As[r][kk] = A[r * 512 + kc * 64 + kk];
    }
    __syncthreads();
    const float* W = jobs.W[job] + (size_t)(kc * 64) * 512;
    float acc0[16], acc1[16];
    #pragma unroll
    for (int r = 0; r < 16; r++) { acc0[r] = 0.f; acc1[r] = 0.f; }
    #pragma unroll 4
    for (int kk = 0; kk < 64; kk++) {
        float w0 = W[kk * 512 + tid];
        float w1 = W[kk * 512 + tid + 256];
        #pragma unroll
        for (int r = 0; r < 16; r++) {
            float a = As[r][kk];
            acc0[r] = fmaf(a, w0, acc0[r]);
            acc1[r] = fmaf(a, w1, acc1[r]);
        }
    }
    float* p = part + ((size_t)job * 8 + kc) * (16 * 512);
    #pragma unroll
    for (int r = 0; r < 16; r++) {
        p[r * 512 + tid]       = acc0[r];
        p[r * 512 + tid + 256] = acc1[r];
    }
}

__global__ void __launch_bounds__(256)
sgemm16_red(SJobs jobs, const float* __restrict__ part) {
    int job = blockIdx.y;
    int i   = blockIdx.x * 256 + threadIdx.x;
    int c   = i & 511;
    const float* p = part + (size_t)job * 8 * (16 * 512) + i;
    float v = jobs.bias[job][c];
    #pragma unroll
    for (int kc = 0; kc < 8; kc++) v += p[kc * (16 * 512)];
    jobs.C[job][i] = v;
}

// ---------------------------------------------------------------------------
// sat attention: 5 keys per token
// ---------------------------------------------------------------------------
__global__ void sat_attn(const float* __restrict__ Q,  int ldq,
                         const float* __restrict__ Kh, const float* __restrict__ Vh,
                         int ldkv,
                         const float* __restrict__ Ke, const float* __restrict__ Ve,
                         int ldke,
                         const float* __restrict__ Ks,  const float* __restrict__ Vs,
                         __nv_bfloat16* __restrict__ chi, __nv_bfloat16* __restrict__ clo) {
    int t = blockIdx.x;
    int b = t >> 9;
    int l = t & 511;
    int head = threadIdx.x >> 5;
    int lane = threadIdx.x & 31;
    int d0 = head * HD + lane;
    int r0 = (b << 9) + ((l + 1) & 511);
    int r2 = (b << 9) + (l == 0 ? (L - 1) : 0);

    const float* qp = Q + (size_t)t * ldq + d0;
    float q0 = qp[0], q1 = qp[32];
    const float* kp[5] = { Kh + (size_t)r0 * ldkv + d0, Kh + (size_t)t * ldkv + d0,
                           Kh + (size_t)r2 * ldkv + d0, Ke + (size_t)t * ldke + d0,
                           Ks + b * D + d0 };
    const float* vp[5] = { Vh + (size_t)r0 * ldkv + d0, Vh + (size_t)t * ldkv + d0,
                           Vh + (size_t)r2 * ldkv + d0, Ve + (size_t)t * ldke + d0,
                           Vs + b * D + d0 };
    float sc[5];
    #pragma unroll
    for (int i = 0; i < 5; i++) {
        float p = q0 * kp[i][0] + q1 * kp[i][32];
        #pragma unroll
        for (int o = 16; o > 0; o >>= 1) p += __shfl_xor_sync(0xffffffffu, p, o);
        sc[i] = p * 0.125f;
    }
    float m = sc[0];
    #pragma unroll
    for (int i = 1; i < 5; i++) m = fmaxf(m, sc[i]);
    float den = 0.f;
    #pragma unroll
    for (int i = 0; i < 5; i++) { sc[i] = expf(sc[i] - m); den += sc[i]; }
    float inv = 1.f / den;
    float o0 = 0.f, o1 = 0.f;
    #pragma unroll
    for (int i = 0; i < 5; i++) {
        o0 = fmaf(sc[i], vp[i][0],  o0);
        o1 = fmaf(sc[i], vp[i][32], o1);
    }
    o0 *= inv; o1 *= inv;
    int base = t * D;
    __nv_bfloat16 h0 = __float2bfloat16_rn(o0);
    __nv_bfloat16 h1 = __float2bfloat16_rn(o1);
    chi[base + d0]      = h0;
    chi[base + d0 + 32] = h1;
    clo[base + d0]      = __float2bfloat16_rn(o0 - __bfloat162float(h0));
    clo[base + d0 + 32] = __float2bfloat16_rn(o1 - __bfloat162float(h1));
}

// ---------------------------------------------------------------------------
// rel attention: 513 keys. KV = g_big (ld 2560, kr @ +1536, vr @ +2048).
// Score pass: warp-per-key, coalesced dim loads + shuffle reduce.
// ---------------------------------------------------------------------------
__global__ void rel_attn(const float* __restrict__ Qs,  const float* __restrict__ Ksr,
                         const float* __restrict__ KV,  const float* __restrict__ Vsr,
                         float* __restrict__ ctxs) {
    __shared__ float sc[513];
    __shared__ float red[256];
    __shared__ float qsh[HD];
    int b    = blockIdx.x >> 3;
    int head = blockIdx.x & 7;
    int tid  = threadIdx.x;
    int warp = tid >> 5;
    int lane = tid & 31;
    int off  = head * HD;

    if (tid < HD) qsh[tid] = Qs[b * D + off + tid];
    __syncthreads();

    // scores: warp w handles keys w, w+8, ...
    float q0 = qsh[lane], q1 = qsh[lane + 32];
    for (int k = warp; k < 513; k += 8) {
        const float* kv = (k == 0) ? (Ksr + b * D + off)
                                   : (KV + (size_t)((b << 9) + k - 1) * 2560 + 1536 + off);
        float p = q0 * kv[lane] + q1 * kv[lane + 32];
        #pragma unroll
        for (int o = 16; o > 0; o >>= 1) p += __shfl_xor_sync(0xffffffffu, p, o);
        if (lane == 0) sc[k] = p * 0.125f;
    }
    __syncthreads();

    float m = -1e30f;
    for (int k = tid; k < 513; k += 256) m = fmaxf(m, sc[k]);
    red[tid] = m; __syncthreads();
    for (int st = 128; st > 0; st >>= 1) {
        if (tid < st) red[tid] = fmaxf(red[tid], red[tid + st]);
        __syncthreads();
    }
    m = red[0];
    __syncthreads();

    float dsum = 0.f;
    for (int k = tid; k < 513; k += 256) {
        float e_ = expf(sc[k] - m);
        sc[k] = e_;
        dsum += e_;
    }
    red[tid] = dsum; __syncthreads();
    for (int st = 128; st > 0; st >>= 1) {
        if (tid < st) red[tid] += red[tid + st];
        __syncthreads();
    }
    float inv = 1.f / red[0];
    __syncthreads();

    int d = tid & 63;
    int g = tid >> 6;
    float acc = 0.f;
    for (int k = g; k < 513; k += 4) {
        const float* vv = (k == 0) ? (Vsr + b * D + off)
                                   : (KV + (size_t)((b << 9) + k - 1) * 2560 + 2048 + off);
        acc = fmaf(sc[k], vv[d], acc);
    }
    red[tid] = acc;
    __syncthreads();
    if (tid < 64) {
        float o = red[tid] + red[tid + 64] + red[tid + 128] + red[tid + 192];
        ctxs[b * D + off + tid] = o * inv;
    }
}

// ---------------------------------------------------------------------------
// relu + LayerNorm (+ optional bf16 split outputs)
// ---------------------------------------------------------------------------
__global__ void relu_ln(const float* __restrict__ x, const float* __restrict__ w,
                        const float* __restrict__ bb, float* __restrict__ out,
                        __nv_bfloat16* __restrict__ hi, __nv_bfloat16* __restrict__ lo) {
    __shared__ float red[256];
    int row = blockIdx.x;
    int tid = threadIdx.x;
    float v0 = fmaxf(x[row * D + tid],       0.f);
    float v1 = fmaxf(x[row * D + tid + 256], 0.f);
    red[tid] = v0 + v1;
    __syncthreads();
    for (int st = 128; st > 0; st >>= 1) {
        if (tid < st) red[tid] += red[tid + st];
        __syncthreads();
    }
    float mean = red[0] * (1.f / 512.f);
    __syncthreads();
    float d0 = v0 - mean, d1 = v1 - mean;
    red[tid] = d0 * d0 + d1 * d1;
    __syncthreads();
    for (int st = 128; st > 0; st >>= 1) {
        if (tid < st) red[tid] += red[tid + st];
        __syncthreads();
    }
    float inv = rsqrtf(red[0] * (1.f / 512.f) + 1e-12f);
    float o0 = w[tid]       * d0 * inv + bb[tid];
    float o1 = w[tid + 256] * d1 * inv + bb[tid + 256];
    out[row * D + tid]       = o0;
    out[row * D + tid + 256] = o1;
    if (hi) {
        __nv_bfloat16 h0 = __float2bfloat16_rn(o0);
        __nv_bfloat16 h1 = __float2bfloat16_rn(o1);
        hi[row * D + tid]       = h0;
        hi[row * D + tid + 256] = h1;
        lo[row * D + tid]       = __float2bfloat16_rn(o0 - __bfloat162float(h0));
        lo[row * D + tid + 256] = __float2bfloat16_rn(o1 - __bfloat162float(h1));
    }
}

// ---------------------------------------------------------------------------
// logits = h @ ofc_w[512,17] + ofc_b
// ---------------------------------------------------------------------------
__global__ void final_logits(const float* __restrict__ h, const float* __restrict__ W,
                             const float* __restrict__ bias, float* __restrict__ out) {
    __shared__ float Wsh[512 * T];
    int tid = threadIdx.x;
    for (int i = tid; i < 512 * T; i += 256) Wsh[i] = W[i];
    __syncthreads();
    int warp = tid >> 5, lane = tid & 31;
    int row = blockIdx.x * 8 + warp;
    float acc[T];
    #pragma unroll
    for (int t = 0; t < T; t++) acc[t] = 0.f;
    const float* hr = h + row * D;
    for (int k = lane; k < D; k += 32) {
        float a = hr[k];
        #pragma unroll
        for (int t = 0; t < T; t++) acc[t] = fmaf(a, Wsh[k * T + t], acc[t]);
    }
    #pragma unroll
    for (int t = 0; t < T; t++)
        #pragma unroll
        for (int o = 16; o > 0; o >>= 1)
            acc[t] += __shfl_xor_sync(0xffffffffu, acc[t], o);
    if (lane == 0) {
        #pragma unroll
        for (int t = 0; t < T; t++) out[row * T + t] = acc[t] + bias[t];
    }
}

// ---------------------------------------------------------------------------
// Launch
// ---------------------------------------------------------------------------
extern "C" void kernel_launch(void* const* d_in, const int* in_sizes, int n_in,
                              void* d_out, int out_size) {
    (void)in_sizes; (void)n_in; (void)out_size;
    const int*   tokens  = (const int*)  d_in[0];
    const float* emb     = (const float*)d_in[4];
    // Reordered slots: sat_q, sat_k, sat_v, rel_k, rel_v, sat_o, rel_q, rel_o
    Ptr8 wsrc = {{ (const float*)d_in[5],  (const float*)d_in[7],
                   (const float*)d_in[9],  (const float*)d_in[15],
                   (const float*)d_in[17], (const float*)d_in[11],
                   (const float*)d_in[13], (const float*)d_in[19] }};
    Ptr8 bsrc = {{ (const float*)d_in[6],  (const float*)d_in[8],
                   (const float*)d_in[10], (const float*)d_in[16],
                   (const float*)d_in[18], (const float*)d_in[12],
                   (const float*)d_in[14], (const float*)d_in[20] }};
    const float* sat_kw = (const float*)d_in[7];
    const float* sat_kb = (const float*)d_in[8];
    const float* sat_vw = (const float*)d_in[9];
    const float* sat_vb = (const float*)d_in[10];
    const float* rel_qw = (const float*)d_in[13];
    const float* rel_qb = (const float*)d_in[14];
    const float* rel_kw = (const float*)d_in[15];
    const float* rel_kb = (const float*)d_in[16];
    const float* rel_vw = (const float*)d_in[17];
    const float* rel_vb = (const float*)d_in[18];
    const float* rel_ow = (const float*)d_in[19];
    const float* rel_ob = (const float*)d_in[20];
    const float* ln_sw  = (const float*)d_in[21];
    const float* ln_sb  = (const float*)d_in[22];
    const float* ln_rw  = (const float*)d_in[23];
    const float* ln_rb  = (const float*)d_in[24];
    const float* ofc_w  = (const float*)d_in[25];
    const float* ofc_b  = (const float*)d_in[26];
    float* out = (float*)d_out;

    float *e, *h, *s, *qkv, *qkeve, *big, *a;
    float *ks, *vs, *qsr, *ksr, *vsr, *ctxs, *r, *bias, *part;
    __nv_bfloat16 *ehi, *elo, *hhi, *hlo, *cthi, *ctlo, *whi, *wlo;
    cudaGetSymbolAddress((void**)&e,     g_e);
    cudaGetSymbolAddress((void**)&h,     g_h);
    cudaGetSymbolAddress((void**)&s,     g_s);
    cudaGetSymbolAddress((void**)&qkv,   g_qkv);
    cudaGetSymbolAddress((void**)&qkeve, g_qkeve);
    cudaGetSymbolAddress((void**)&big,   g_big);
    cudaGetSymbolAddress((void**)&a,     g_a);
    cudaGetSymbolAddress((void**)&ks,    g_ks);
    cudaGetSymbolAddress((void**)&vs,    g_vs);
    cudaGetSymbolAddress((void**)&qsr,   g_qsr);
    cudaGetSymbolAddress((void**)&ksr,   g_ksr);
    cudaGetSymbolAddress((void**)&vsr,   g_vsr);
    cudaGetSymbolAddress((void**)&ctxs,  g_ctxs);
    cudaGetSymbolAddress((void**)&r,     g_r);
    cudaGetSymbolAddress((void**)&bias,  g_bias);
    cudaGetSymbolAddress((void**)&part,  g_part);
    cudaGetSymbolAddress((void**)&ehi,   g_ehi);
    cudaGetSymbolAddress((void**)&elo,   g_elo);
    cudaGetSymbolAddress((void**)&hhi,   g_hhi);
    cudaGetSymbolAddress((void**)&hlo,   g_hlo);
    cudaGetSymbolAddress((void**)&cthi,  g_cthi);
    cudaGetSymbolAddress((void**)&ctlo,  g_ctlo);
    cudaGetSymbolAddress((void**)&whi,   g_whi);
    cudaGetSymbolAddress((void**)&wlo,   g_wlo);

    cudaFuncSetAttribute(mma_gemm, cudaFuncAttributeMaxDynamicSharedMemorySize,
                         SMEM_BYTES);

    #define GEMM(AHI, ALO, WI, NTOT, OUT, LDC)                                 \
        mma_gemm<<<dim3((NTOT) / 128, 64), 256, SMEM_BYTES>>>(                 \
            AHI, ALO, whi + (WI) * DD, wlo + (WI) * DD, bias + (WI) * 512,     \
            OUT, LDC)

    #define SMALL(AIN, JOBS, NJ)                                               \
        do {                                                                   \
            sgemm16_part<<<dim3(8, NJ), 256>>>(AIN, JOBS, part);               \
            sgemm16_red<<<dim3(32, NJ), 256>>>(JOBS, part);                    \
        } while (0)

    // Weight prep
    wsplit_all<<<dim3(16, 16, 8), dim3(32, 8)>>>(wsrc, whi, wlo);
    biascat<<<16, 256>>>(bsrc, bias);

    embed_split<<<BL * D / 256, 256>>>(tokens, emb, e, ehi, elo);

    // Cycle-0 fused projection from e: q | ke | ve (slots 0-2). ncu slot.
    GEMM(ehi, elo, 0, 1536, qkeve, 1536);

    smean_kernel<<<B * 8, 256>>>(e, s);

    // All 5 s-projections for cycle 0 (sat ks/vs + rel qsr/ksr/vsr) in one pair
    {
        SJobs j = {{ sat_kw, sat_vw, rel_qw, rel_kw, rel_vw },
                   { sat_kb, sat_vb, rel_qb, rel_kb, rel_vb },
                   { ks, vs, qsr, ksr, vsr }};
        SMALL(s, j, 5);
    }

    // ---- cycle 0 ----
    sat_attn<<<BL, 256>>>(qkeve, 1536,
                          qkeve + 512, qkeve + 1024, 1536,
                          qkeve + 512, qkeve + 1024, 1536,
                          ks, vs, cthi, ctlo);
    GEMM(cthi, ctlo, 5, 512, a, 512);              // sat_o (slot 5)
    relu_ln<<<BL, 256>>>(a, ln_sw, ln_sb, h, hhi, hlo);

    // Merged h projections: q|k|v|kr|vr (slots 0-4, contiguous) — N=2560
    GEMM(hhi, hlo, 0, 2560, big, 2560);

    // rel path (cycle 0)
    rel_attn<<<B * NH, 256>>>(qsr, ksr, big, vsr, ctxs);
    {
        SJobs j = {{ rel_ow, nullptr, nullptr, nullptr, nullptr },
                   { rel_ob, nullptr, nullptr, nullptr, nullptr },
                   { r, nullptr, nullptr, nullptr, nullptr }};
        SMALL(ctxs, j, 1);
    }
    relu_ln<<<B, 256>>>(r, ln_rw, ln_rb, s, nullptr, nullptr);

    // ---- cycle 1 (last: rel path dead) ----
    {
        SJobs j = {{ sat_kw, sat_vw, nullptr, nullptr, nullptr },
                   { sat_kb, sat_vb, nullptr, nullptr, nullptr },
                   { ks, vs, nullptr, nullptr, nullptr }};
        SMALL(s, j, 2);
    }
    sat_attn<<<BL, 256>>>(big, 2560,
                          big + 512, big + 1024, 2560,
                          qkeve + 512, qkeve + 1024, 1536,
                          ks, vs, cthi, ctlo);
    GEMM(cthi, ctlo, 5, 512, a, 512);              // sat_o
    relu_ln<<<BL, 256>>>(a, ln_sw, ln_sb, h, nullptr, nullptr);

    final_logits<<<BL / 8, 256>>>(h, ofc_w, ofc_b, out);
}

// round 13
// speedup vs baseline: 1.4575x; 1.4575x over previous
#include <cuda_runtime.h>
#include <cuda_bf16.h>
#include <cstdint>
#include <math.h>

// Problem constants
#define B   16
#define L   512
#define D   512
#define NH  8
#define HD  64
#define T   17
#define CYC 2
#define BL  (B * L)   // 8192
#define DD  (D * D)

// Weight slots (transposed buffer): 0 sat_q, 1 sat_k, 2 sat_v, 3 sat_o,
//                                   4 rel_q, 5 rel_k, 6 rel_v, 7 rel_o
// ---------------------------------------------------------------------------
// Scratch (device globals)
// ---------------------------------------------------------------------------
__device__ float g_e[BL * D];
__device__ float g_h[BL * D];
__device__ float g_s[B * D];
__device__ float g_qkv[BL * 1536];    // cyc1: q | k | v
__device__ float g_qkeve[BL * 1536];  // cyc0: q | ke | ve
__device__ float g_krvr[BL * 1024];   // kr | vr
__device__ float g_a[BL * D];
__device__ float g_ks[B * D];
__device__ float g_vs[B * D];
__device__ float g_qsr[B * D];
__device__ float g_ksr[B * D];
__device__ float g_vsr[B * D];
__device__ float g_ctxs[B * D];
__device__ float g_r[B * D];
__device__ float g_bias[8 * D];
__device__ float g_part[5 * 8 * 16 * 512];   // small-gemm K-split partials

// bf16 split buffers (16B aligned for cp.async 16)
__device__ __align__(16) __nv_bfloat16 g_ehi[BL * D];
__device__ __align__(16) __nv_bfloat16 g_elo[BL * D];
__device__ __align__(16) __nv_bfloat16 g_hhi[BL * D];
__device__ __align__(16) __nv_bfloat16 g_hlo[BL * D];
__device__ __align__(16) __nv_bfloat16 g_cthi[BL * D];
__device__ __align__(16) __nv_bfloat16 g_ctlo[BL * D];
__device__ __align__(16) __nv_bfloat16 g_whi[8 * DD];   // transposed [N][K]
__device__ __align__(16) __nv_bfloat16 g_wlo[8 * DD];

struct Ptr8 { const float* p[8]; };
struct SJobs { const float* W[5]; const float* bias[5]; float* C[5]; };

// ---------------------------------------------------------------------------
// Embedding: e fp32 + split bf16
// ---------------------------------------------------------------------------
__global__ void embed_split(const int* __restrict__ tokens,
                            const float* __restrict__ emb,
                            float* __restrict__ e,
                            __nv_bfloat16* __restrict__ hi,
                            __nv_bfloat16* __restrict__ lo) {
    int idx = blockIdx.x * 256 + threadIdx.x;
    int row = idx / D;
    int d   = idx - row * D;
    float v = emb[tokens[row] * D + d];
    e[idx] = v;
    __nv_bfloat16 hv = __float2bfloat16_rn(v);
    hi[idx] = hv;
    lo[idx] = __float2bfloat16_rn(v - __bfloat162float(hv));
}

// s[b,d] = mean_l e[b,l,d]
__global__ void smean_kernel(const float* __restrict__ e, float* __restrict__ s) {
    __shared__ float red[256];
    int b     = blockIdx.x >> 3;
    int dbase = (blockIdx.x & 7) * 64;
    int tid   = threadIdx.x;
    int d     = dbase + (tid & 63);
    int grp   = tid >> 6;
    const float* p = e + ((b << 9) + grp * 128) * D + d;
    float acc = 0.f;
    #pragma unroll 8
    for (int l = 0; l < 128; l++) acc += p[l * D];
    red[tid] = acc;
    __syncthreads();
    if (tid < 128) red[tid] += red[tid + 128];
    __syncthreads();
    if (tid < 64)
        s[b * D + d] = (red[tid] + red[tid + 64]) * (1.f / (float)L);
}

// ---------------------------------------------------------------------------
// Weight prep: split + transpose all 8 weights; concat biases
// ---------------------------------------------------------------------------
__global__ void wsplit_all(Ptr8 W, __nv_bfloat16* __restrict__ hi,
                           __nv_bfloat16* __restrict__ lo) {
    __shared__ float t[32][33];
    const float* Wsrc = W.p[blockIdx.z];
    __nv_bfloat16* hz = hi + blockIdx.z * DD;
    __nv_bfloat16* lz = lo + blockIdx.z * DD;
    int bx = blockIdx.x, by = blockIdx.y;
    int x = threadIdx.x, y = threadIdx.y;
    #pragma unroll
    for (int j = 0; j < 32; j += 8)
        t[y + j][x] = Wsrc[(by * 32 + y + j) * 512 + bx * 32 + x];
    __syncthreads();
    #pragma unroll
    for (int j = 0; j < 32; j += 8) {
        float v = t[x][y + j];
        int n = bx * 32 + y + j;
        int k = by * 32 + x;
        __nv_bfloat16 hv = __float2bfloat16_rn(v);
        hz[n * 512 + k] = hv;
        lz[n * 512 + k] = __float2bfloat16_rn(v - __bfloat162float(hv));
    }
}

__global__ void biascat(Ptr8 bsrc, float* __restrict__ dst) {
    int i = blockIdx.x * 256 + threadIdx.x;
    dst[i] = bsrc.p[i >> 9][i & 511];
}

// ---------------------------------------------------------------------------
// Tensor-core GEMM (R11 exact — best measured):
// C[8192,N] = A[8192,512] @ Wt[N,512]^T + bias
// 3-term bf16 split; ldmatrix; 128x128x32 tiles, 2-stage cp.async,
// single sync per K-iter, warp phase stagger.
// ---------------------------------------------------------------------------
#define SMEM_STAGE 20480
#define SMEM_BYTES (2 * SMEM_STAGE * 2)

__device__ __forceinline__ void mma16816(float* d, const uint32_t* a,
                                         const uint32_t* b) {
    asm volatile("mma.sync.aligned.m16n8k16.row.col.f32.bf16.bf16.f32 "
                 "{%0,%1,%2,%3}, {%4,%5,%6,%7}, {%8,%9}, {%0,%1,%2,%3};"
                 : "+f"(d[0]), "+f"(d[1]), "+f"(d[2]), "+f"(d[3])
                 : "r"(a[0]), "r"(a[1]), "r"(a[2]), "r"(a[3]),
                   "r"(b[0]), "r"(b[1]));
}

__device__ __forceinline__ void ldsm_x4(uint32_t* r, uint32_t a) {
    asm volatile("ldmatrix.sync.aligned.m8n8.x4.shared.b16 {%0,%1,%2,%3}, [%4];"
                 : "=r"(r[0]), "=r"(r[1]), "=r"(r[2]), "=r"(r[3]) : "r"(a));
}

__global__ void __launch_bounds__(256, 2)
mma_gemm(const __nv_bfloat16* __restrict__ Ahi, const __nv_bfloat16* __restrict__ Alo,
         const __nv_bfloat16* __restrict__ Whi, const __nv_bfloat16* __restrict__ Wlo,
         const float* __restrict__ bias, float* __restrict__ C, int ldc) {
    extern __shared__ __nv_bfloat16 sm[];
    const int tid  = threadIdx.x;
    const int lane = tid & 31;
    const int warp = tid >> 5;
    const int wm = warp >> 2;
    const int wn = warp & 3;
    const int m0 = blockIdx.y * 128;
    const int n0 = blockIdx.x * 128;
    const int sks = warp & 1;

    float acc[4][4][4];
    #pragma unroll
    for (int i = 0; i < 4; i++)
        #pragma unroll
        for (int j = 0; j < 4; j++)
            #pragma unroll
            for (int t = 0; t < 4; t++) acc[i][j][t] = 0.f;

    uint32_t smbase = (uint32_t)__cvta_generic_to_shared(sm);

    auto load_stage = [&](int s, int k0) {
        uint32_t base = smbase + (uint32_t)(s * SMEM_STAGE * 2);
        #pragma unroll
        for (int i = 0; i < 2; i++) {
            int id  = tid + i * 256;
            int row = id >> 2;
            int qc  = (id & 3) << 3;
            uint32_t so = base + (uint32_t)((row * 40 + qc) * 2);
            const __nv_bfloat16* ga = Ahi + (m0 + row) * 512 + k0 + qc;
            const __nv_bfloat16* gb = Alo + (m0 + row) * 512 + k0 + qc;
            const __nv_bfloat16* gc = Whi + (n0 + row) * 512 + k0 + qc;
            const __nv_bfloat16* gd = Wlo + (n0 + row) * 512 + k0 + qc;
            asm volatile("cp.async.cg.shared.global [%0], [%1], 16;" :: "r"(so),           "l"(ga));
            asm volatile("cp.async.cg.shared.global [%0], [%1], 16;" :: "r"(so + 10240u), "l"(gb));
            asm volatile("cp.async.cg.shared.global [%0], [%1], 16;" :: "r"(so + 20480u), "l"(gc));
            asm volatile("cp.async.cg.shared.global [%0], [%1], 16;" :: "r"(so + 30720u), "l"(gd));
        }
    };

    load_stage(0, 0);
    asm volatile("cp.async.commit_group;");

    const int lrow  = lane & 15;
    const int lkoff = (lane >> 4) << 3;

    #pragma unroll 1
    for (int it = 0; it < 16; it++) {
        asm volatile("cp.async.wait_group 0;");
        __syncthreads();
        if (it < 15) {
            load_stage((it + 1) & 1, (it + 1) * 32);
            asm volatile("cp.async.commit_group;");
        }

        uint32_t st = smbase + (uint32_t)((it & 1) * SMEM_STAGE * 2);

        #pragma unroll
        for (int s = 0; s < 2; s++) {
            int ks = s ^ sks;
            int col = ks * 16 + lkoff;
            uint32_t bh[4][2], bl[4][2];
            #pragma unroll
            for (int ntp = 0; ntp < 2; ntp++) {
                int n = wn * 32 + ntp * 16 + lrow;
                uint32_t adr = st + 20480u + (uint32_t)((n * 40 + col) * 2);
                uint32_t t4[4];
                ldsm_x4(t4, adr);
                bh[ntp * 2 + 0][0] = t4[0]; bh[ntp * 2 + 0][1] = t4[2];
                bh[ntp * 2 + 1][0] = t4[1]; bh[ntp * 2 + 1][1] = t4[3];
                ldsm_x4(t4, adr + 10240u);
                bl[ntp * 2 + 0][0] = t4[0]; bl[ntp * 2 + 0][1] = t4[2];
                bl[ntp * 2 + 1][0] = t4[1]; bl[ntp * 2 + 1][1] = t4[3];
            }
            #pragma unroll
            for (int mt = 0; mt < 4; mt++) {
                int row = wm * 64 + mt * 16 + lrow;
                uint32_t adr = st + (uint32_t)((row * 40 + col) * 2);
                uint32_t ah[4], al[4];
                ldsm_x4(ah, adr);
                ldsm_x4(al, adr + 10240u);
                #pragma unroll
                for (int nt = 0; nt < 4; nt++) {
                    mma16816(acc[mt][nt], ah, bh[nt]);
                    mma16816(acc[mt][nt], ah, bl[nt]);
                    mma16816(acc[mt][nt], al, bh[nt]);
                }
            }
        }
    }

    const int r = lane >> 2;
    const int c = (lane & 3) << 1;
    #pragma unroll
    for (int mt = 0; mt < 4; mt++) {
        #pragma unroll
        for (int nt = 0; nt < 4; nt++) {
            int row = m0 + wm * 64 + mt * 16 + r;
            int col = n0 + wn * 32 + nt * 8 + c;
            float b0 = bias[col], b1 = bias[col + 1];
            float2 v0 = make_float2(acc[mt][nt][0] + b0, acc[mt][nt][1] + b1);
            float2 v1 = make_float2(acc[mt][nt][2] + b0, acc[mt][nt][3] + b1);
            *(float2*)(C + row * ldc + col)       = v0;
            *(float2*)(C + (row + 8) * ldc + col) = v1;
        }
    }
}

// ---------------------------------------------------------------------------
// Small GEMM, K-split 2-phase (deterministic); up to 5 jobs per launch
// ---------------------------------------------------------------------------
__global__ void __launch_bounds__(256)
sgemm16_part(const float* __restrict__ A, SJobs jobs, float* __restrict__ part) {
    __shared__ float As[16][64];
    int kc  = blockIdx.x;
    int job = blockIdx.y;
    int tid = threadIdx.x;
    for (int i = tid; i < 16 * 64; i += 256) {
        int r = i >> 6, kk = i & 63;
        As[r][kk] = A[r * 512 + kc * 64 + kk];
    }
    __syncthreads();
    const float* W = jobs.W[job] + (size_t)(kc * 64) * 512;
    float acc0[16], acc1[16];
    #pragma unroll
    for (int r = 0; r < 16; r++) { acc0[r] = 0.f; acc1[r] = 0.f; }
    #pragma unroll 4
    for (int kk = 0; kk < 64; kk++) {
        float w0 = W[kk * 512 + tid];
        float w1 = W[kk * 512 + tid + 256];
        #pragma unroll
        for (int r = 0; r < 16; r++) {
            float a = As[r][kk];
            acc0[r] = fmaf(a, w0, acc0[r]);
            acc1[r] = fmaf(a, w1, acc1[r]);
        }
    }
    float* p = part + ((size_t)job * 8 + kc) * (16 * 512);
    #pragma unroll
    for (int r = 0; r < 16; r++) {
        p[r * 512 + tid]       = acc0[r];
        p[r * 512 + tid + 256] = acc1[r];
    }
}

__global__ void __launch_bounds__(256)
sgemm16_red(SJobs jobs, const float* __restrict__ part) {
    int job = blockIdx.y;
    int i   = blockIdx.x * 256 + threadIdx.x;
    int c   = i & 511;
    const float* p = part + (size_t)job * 8 * (16 * 512) + i;
    float v = jobs.bias[job][c];
    #pragma unroll
    for (int kc = 0; kc < 8; kc++) v += p[kc * (16 * 512)];
    jobs.C[job][i] = v;
}

// ---------------------------------------------------------------------------
// sat attention: 5 keys per token
// ---------------------------------------------------------------------------
__global__ void sat_attn(const float* __restrict__ Q,  int ldq,
                         const float* __restrict__ Kh, const float* __restrict__ Vh,
                         int ldkv,
                         const float* __restrict__ Ke, const float* __restrict__ Ve,
                         int ldke,
                         const float* __restrict__ Ks,  const float* __restrict__ Vs,
                         __nv_bfloat16* __restrict__ chi, __nv_bfloat16* __restrict__ clo) {
    int t = blockIdx.x;
    int b = t >> 9;
    int l = t & 511;
    int head = threadIdx.x >> 5;
    int lane = threadIdx.x & 31;
    int d0 = head * HD + lane;
    int r0 = (b << 9) + ((l + 1) & 511);
    int r2 = (b << 9) + (l == 0 ? (L - 1) : 0);

    const float* qp = Q + (size_t)t * ldq + d0;
    float q0 = qp[0], q1 = qp[32];
    const float* kp[5] = { Kh + (size_t)r0 * ldkv + d0, Kh + (size_t)t * ldkv + d0,
                           Kh + (size_t)r2 * ldkv + d0, Ke + (size_t)t * ldke + d0,
                           Ks + b * D + d0 };
    const float* vp[5] = { Vh + (size_t)r0 * ldkv + d0, Vh + (size_t)t * ldkv + d0,
                           Vh + (size_t)r2 * ldkv + d0, Ve + (size_t)t * ldke + d0,
                           Vs + b * D + d0 };
    float sc[5];
    #pragma unroll
    for (int i = 0; i < 5; i++) {
        float p = q0 * kp[i][0] + q1 * kp[i][32];
        #pragma unroll
        for (int o = 16; o > 0; o >>= 1) p += __shfl_xor_sync(0xffffffffu, p, o);
        sc[i] = p * 0.125f;
    }
    float m = sc[0];
    #pragma unroll
    for (int i = 1; i < 5; i++) m = fmaxf(m, sc[i]);
    float den = 0.f;
    #pragma unroll
    for (int i = 0; i < 5; i++) { sc[i] = expf(sc[i] - m); den += sc[i]; }
    float inv = 1.f / den;
    float o0 = 0.f, o1 = 0.f;
    #pragma unroll
    for (int i = 0; i < 5; i++) {
        o0 = fmaf(sc[i], vp[i][0],  o0);
        o1 = fmaf(sc[i], vp[i][32], o1);
    }
    o0 *= inv; o1 *= inv;
    int base = t * D;
    __nv_bfloat16 h0 = __float2bfloat16_rn(o0);
    __nv_bfloat16 h1 = __float2bfloat16_rn(o1);
    chi[base + d0]      = h0;
    chi[base + d0 + 32] = h1;
    clo[base + d0]      = __float2bfloat16_rn(o0 - __bfloat162float(h0));
    clo[base + d0 + 32] = __float2bfloat16_rn(o1 - __bfloat162float(h1));
}

// ---------------------------------------------------------------------------
// rel attention: 513 keys; krvr layout (ld 1024, kr@0, vr@+512).
// Score pass: warp-per-key, coalesced dim loads + shuffle reduce.
// ---------------------------------------------------------------------------
__global__ void rel_attn(const float* __restrict__ Qs,  const float* __restrict__ Ksr,
                         const float* __restrict__ KrVr, const float* __restrict__ Vsr,
                         float* __restrict__ ctxs) {
    __shared__ float sc[513];
    __shared__ float red[256];
    __shared__ float qsh[HD];
    int b    = blockIdx.x >> 3;
    int head = blockIdx.x & 7;
    int tid  = threadIdx.x;
    int warp = tid >> 5;
    int lane = tid & 31;
    int off  = head * HD;

    if (tid < HD) qsh[tid] = Qs[b * D + off + tid];
    __syncthreads();

    float q0 = qsh[lane], q1 = qsh[lane + 32];
    for (int k = warp; k < 513; k += 8) {
        const float* kv = (k == 0) ? (Ksr + b * D + off)
                                   : (KrVr + (size_t)((b << 9) + k - 1) * 1024 + off);
        float p = q0 * kv[lane] + q1 * kv[lane + 32];
        #pragma unroll
        for (int o = 16; o > 0; o >>= 1) p += __shfl_xor_sync(0xffffffffu, p, o);
        if (lane == 0) sc[k] = p * 0.125f;
    }
    __syncthreads();

    float m = -1e30f;
    for (int k = tid; k < 513; k += 256) m = fmaxf(m, sc[k]);
    red[tid] = m; __syncthreads();
    for (int st = 128; st > 0; st >>= 1) {
        if (tid < st) red[tid] = fmaxf(red[tid], red[tid + st]);
        __syncthreads();
    }
    m = red[0];
    __syncthreads();

    float dsum = 0.f;
    for (int k = tid; k < 513; k += 256) {
        float e_ = expf(sc[k] - m);
        sc[k] = e_;
        dsum += e_;
    }
    red[tid] = dsum; __syncthreads();
    for (int st = 128; st > 0; st >>= 1) {
        if (tid < st) red[tid] += red[tid + st];
        __syncthreads();
    }
    float inv = 1.f / red[0];
    __syncthreads();

    int d = tid & 63;
    int g = tid >> 6;
    float acc = 0.f;
    for (int k = g; k < 513; k += 4) {
        const float* vv = (k == 0) ? (Vsr + b * D + off)
                                   : (KrVr + (size_t)((b << 9) + k - 1) * 1024 + 512 + off);
        acc = fmaf(sc[k], vv[d], acc);
    }
    red[tid] = acc;
    __syncthreads();
    if (tid < 64) {
        float o = red[tid] + red[tid + 64] + red[tid + 128] + red[tid + 192];
        ctxs[b * D + off + tid] = o * inv;
    }
}

// ---------------------------------------------------------------------------
// relu + LayerNorm (+ optional bf16 split outputs)
// ---------------------------------------------------------------------------
__global__ void relu_ln(const float* __restrict__ x, const float* __restrict__ w,
                        const float* __restrict__ bb, float* __restrict__ out,
                        __nv_bfloat16* __restrict__ hi, __nv_bfloat16* __restrict__ lo) {
    __shared__ float red[256];
    int row = blockIdx.x;
    int tid = threadIdx.x;
    float v0 = fmaxf(x[row * D + tid],       0.f);
    float v1 = fmaxf(x[row * D + tid + 256], 0.f);
    red[tid] = v0 + v1;
    __syncthreads();
    for (int st = 128; st > 0; st >>= 1) {
        if (tid < st) red[tid] += red[tid + st];
        __syncthreads();
    }
    float mean = red[0] * (1.f / 512.f);
    __syncthreads();
    float d0 = v0 - mean, d1 = v1 - mean;
    red[tid] = d0 * d0 + d1 * d1;
    __syncthreads();
    for (int st = 128; st > 0; st >>= 1) {
        if (tid < st) red[tid] += red[tid + st];
        __syncthreads();
    }
    float inv = rsqrtf(red[0] * (1.f / 512.f) + 1e-12f);
    float o0 = w[tid]       * d0 * inv + bb[tid];
    float o1 = w[tid + 256] * d1 * inv + bb[tid + 256];
    out[row * D + tid]       = o0;
    out[row * D + tid + 256] = o1;
    if (hi) {
        __nv_bfloat16 h0 = __float2bfloat16_rn(o0);
        __nv_bfloat16 h1 = __float2bfloat16_rn(o1);
        hi[row * D + tid]       = h0;
        hi[row * D + tid + 256] = h1;
        lo[row * D + tid]       = __float2bfloat16_rn(o0 - __bfloat162float(h0));
        lo[row * D + tid + 256] = __float2bfloat16_rn(o1 - __bfloat162float(h1));
    }
}

// ---------------------------------------------------------------------------
// logits = h @ ofc_w[512,17] + ofc_b
// ---------------------------------------------------------------------------
__global__ void final_logits(const float* __restrict__ h, const float* __restrict__ W,
                             const float* __restrict__ bias, float* __restrict__ out) {
    __shared__ float Wsh[512 * T];
    int tid = threadIdx.x;
    for (int i = tid; i < 512 * T; i += 256) Wsh[i] = W[i];
    __syncthreads();
    int warp = tid >> 5, lane = tid & 31;
    int row = blockIdx.x * 8 + warp;
    float acc[T];
    #pragma unroll
    for (int t = 0; t < T; t++) acc[t] = 0.f;
    const float* hr = h + row * D;
    for (int k = lane; k < D; k += 32) {
        float a = hr[k];
        #pragma unroll
        for (int t = 0; t < T; t++) acc[t] = fmaf(a, Wsh[k * T + t], acc[t]);
    }
    #pragma unroll
    for (int t = 0; t < T; t++)
        #pragma unroll
        for (int o = 16; o > 0; o >>= 1)
            acc[t] += __shfl_xor_sync(0xffffffffu, acc[t], o);
    if (lane == 0) {
        #pragma unroll
        for (int t = 0; t < T; t++) out[row * T + t] = acc[t] + bias[t];
    }
}

// ---------------------------------------------------------------------------
// Launch
// ---------------------------------------------------------------------------
extern "C" void kernel_launch(void* const* d_in, const int* in_sizes, int n_in,
                              void* d_out, int out_size) {
    (void)in_sizes; (void)n_in; (void)out_size;
    const int*   tokens  = (const int*)  d_in[0];
    const float* emb     = (const float*)d_in[4];
    Ptr8 wsrc = {{ (const float*)d_in[5],  (const float*)d_in[7],
                   (const float*)d_in[9],  (const float*)d_in[11],
                   (const float*)d_in[13], (const float*)d_in[15],
                   (const float*)d_in[17], (const float*)d_in[19] }};
    Ptr8 bsrc = {{ (const float*)d_in[6],  (const float*)d_in[8],
                   (const float*)d_in[10], (const float*)d_in[12],
                   (const float*)d_in[14], (const float*)d_in[16],
                   (const float*)d_in[18], (const float*)d_in[20] }};
    const float* sat_kw = (const float*)d_in[7];
    const float* sat_kb = (const float*)d_in[8];
    const float* sat_vw = (const float*)d_in[9];
    const float* sat_vb = (const float*)d_in[10];
    const float* rel_qw = (const float*)d_in[13];
    const float* rel_qb = (const float*)d_in[14];
    const float* rel_kw = (const float*)d_in[15];
    const float* rel_kb = (const float*)d_in[16];
    const float* rel_vw = (const float*)d_in[17];
    const float* rel_vb = (const float*)d_in[18];
    const float* rel_ow = (const float*)d_in[19];
    const float* rel_ob = (const float*)d_in[20];
    const float* ln_sw  = (const float*)d_in[21];
    const float* ln_sb  = (const float*)d_in[22];
    const float* ln_rw  = (const float*)d_in[23];
    const float* ln_rb  = (const float*)d_in[24];
    const float* ofc_w  = (const float*)d_in[25];
    const float* ofc_b  = (const float*)d_in[26];
    float* out = (float*)d_out;

    float *e, *h, *s, *qkv, *qkeve, *krvr, *a;
    float *ks, *vs, *qsr, *ksr, *vsr, *ctxs, *r, *bias, *part;
    __nv_bfloat16 *ehi, *elo, *hhi, *hlo, *cthi, *ctlo, *whi, *wlo;
    cudaGetSymbolAddress((void**)&e,     g_e);
    cudaGetSymbolAddress((void**)&h,     g_h);
    cudaGetSymbolAddress((void**)&s,     g_s);
    cudaGetSymbolAddress((void**)&qkv,   g_qkv);
    cudaGetSymbolAddress((void**)&qkeve, g_qkeve);
    cudaGetSymbolAddress((void**)&krvr,  g_krvr);
    cudaGetSymbolAddress((void**)&a,     g_a);
    cudaGetSymbolAddress((void**)&ks,    g_ks);
    cudaGetSymbolAddress((void**)&vs,    g_vs);
    cudaGetSymbolAddress((void**)&qsr,   g_qsr);
    cudaGetSymbolAddress((void**)&ksr,   g_ksr);
    cudaGetSymbolAddress((void**)&vsr,   g_vsr);
    cudaGetSymbolAddress((void**)&ctxs,  g_ctxs);
    cudaGetSymbolAddress((void**)&r,     g_r);
    cudaGetSymbolAddress((void**)&bias,  g_bias);
    cudaGetSymbolAddress((void**)&part,  g_part);
    cudaGetSymbolAddress((void**)&ehi,   g_ehi);
    cudaGetSymbolAddress((void**)&elo,   g_elo);
    cudaGetSymbolAddress((void**)&hhi,   g_hhi);
    cudaGetSymbolAddress((void**)&hlo,   g_hlo);
    cudaGetSymbolAddress((void**)&cthi,  g_cthi);
    cudaGetSymbolAddress((void**)&ctlo,  g_ctlo);
    cudaGetSymbolAddress((void**)&whi,   g_whi);
    cudaGetSymbolAddress((void**)&wlo,   g_wlo);

    cudaFuncSetAttribute(mma_gemm, cudaFuncAttributeMaxDynamicSharedMemorySize,
                         SMEM_BYTES);

    #define GEMM(AHI, ALO, WI, NTOT, OUT, LDC)                                 \
        mma_gemm<<<dim3((NTOT) / 128, 64), 256, SMEM_BYTES>>>(                 \
            AHI, ALO, whi + (WI) * DD, wlo + (WI) * DD, bias + (WI) * 512,     \
            OUT, LDC)

    #define SMALL(AIN, JOBS, NJ)                                               \
        do {                                                                   \
            sgemm16_part<<<dim3(8, NJ), 256>>>(AIN, JOBS, part);               \
            sgemm16_red<<<dim3(32, NJ), 256>>>(JOBS, part);                    \
        } while (0)

    // Weight prep
    wsplit_all<<<dim3(16, 16, 8), dim3(32, 8)>>>(wsrc, whi, wlo);
    biascat<<<16, 256>>>(bsrc, bias);

    embed_split<<<BL * D / 256, 256>>>(tokens, emb, e, ehi, elo);

    // Cycle-0 fused projection from e: q | ke | ve (slots 0-2). ncu slot.
    GEMM(ehi, elo, 0, 1536, qkeve, 1536);

    smean_kernel<<<B * 8, 256>>>(e, s);

    // ---- cycle 0 ----
    // All 5 s-projections (sat ks/vs + rel qsr/ksr/vsr) in one pair
    {
        SJobs j = {{ sat_kw, sat_vw, rel_qw, rel_kw, rel_vw },
                   { sat_kb, sat_vb, rel_qb, rel_kb, rel_vb },
                   { ks, vs, qsr, ksr, vsr }};
        SMALL(s, j, 5);
    }

    sat_attn<<<BL, 256>>>(qkeve, 1536,
                          qkeve + 512, qkeve + 1024, 1536,
                          qkeve + 512, qkeve + 1024, 1536,
                          ks, vs, cthi, ctlo);
    GEMM(cthi, ctlo, 3, 512, a, 512);              // sat_o
    relu_ln<<<BL, 256>>>(a, ln_sw, ln_sb, h, hhi, hlo);

    GEMM(hhi, hlo, 5, 1024, krvr, 1024);           // rel_k | rel_v

    rel_attn<<<B * NH, 256>>>(qsr, ksr, krvr, vsr, ctxs);
    {
        SJobs j = {{ rel_ow, nullptr, nullptr, nullptr, nullptr },
                   { rel_ob, nullptr, nullptr, nullptr, nullptr },
                   { r, nullptr, nullptr, nullptr, nullptr }};
        SMALL(ctxs, j, 1);
    }
    relu_ln<<<B, 256>>>(r, ln_rw, ln_rb, s, nullptr, nullptr);

    // ---- cycle 1 (last: rel path dead) ----
    {
        SJobs j = {{ sat_kw, sat_vw, nullptr, nullptr, nullptr },
                   { sat_kb, sat_vb, nullptr, nullptr, nullptr },
                   { ks, vs, nullptr, nullptr, nullptr }};
        SMALL(s, j, 2);
    }
    GEMM(hhi, hlo, 0, 1536, qkv, 1536);            // q | k | v
    sat_attn<<<BL, 256>>>(qkv, 1536,
                          qkv + 512, qkv + 1024, 1536,
                          qkeve + 512, qkeve + 1024, 1536,
                          ks, vs, cthi, ctlo);
    GEMM(cthi, ctlo, 3, 512, a, 512);              // sat_o
    relu_ln<<<BL, 256>>>(a, ln_sw, ln_sb, h, nullptr, nullptr);

    final_logits<<<BL / 8, 256>>>(h, ofc_w, ofc_b, out);
}

// round 14
// speedup vs baseline: 1.5752x; 1.0808x over previous
#include <cuda_runtime.h>
#include <cuda_bf16.h>
#include <cstdint>
#include <math.h>

// Problem constants
#define B   16
#define L   512
#define D   512
#define NH  8
#define HD  64
#define T   17
#define CYC 2
#define BL  (B * L)   // 8192
#define DD  (D * D)

// Weight slots (transposed buffer): 0 sat_q, 1 sat_k, 2 sat_v, 3 sat_o,
//                                   4 rel_q, 5 rel_k, 6 rel_v, 7 rel_o
// ---------------------------------------------------------------------------
// Scratch (device globals)
// ---------------------------------------------------------------------------
__device__ float g_e[BL * D];
__device__ float g_h[BL * D];
__device__ float g_s[B * D];
__device__ float g_qkv[BL * 1536];    // cyc1: q | k | v
__device__ float g_qkeve[BL * 1536];  // cyc0: q | ke | ve
__device__ float g_krvr[BL * 1024];   // kr | vr
__device__ float g_a[BL * D];
__device__ float g_ks[B * D];
__device__ float g_vs[B * D];
__device__ float g_qsr[B * D];
__device__ float g_ksr[B * D];
__device__ float g_vsr[B * D];
__device__ float g_ctxs[B * D];
__device__ float g_r[B * D];
__device__ float g_bias[8 * D];
__device__ float g_part[5 * 8 * 16 * 512];   // small-gemm K-split partials

// bf16 split buffers (16B aligned for cp.async 16)
__device__ __align__(16) __nv_bfloat16 g_ehi[BL * D];
__device__ __align__(16) __nv_bfloat16 g_elo[BL * D];
__device__ __align__(16) __nv_bfloat16 g_hhi[BL * D];
__device__ __align__(16) __nv_bfloat16 g_hlo[BL * D];
__device__ __align__(16) __nv_bfloat16 g_cthi[BL * D];
__device__ __align__(16) __nv_bfloat16 g_ctlo[BL * D];
__device__ __align__(16) __nv_bfloat16 g_whi[8 * DD];   // transposed [N][K]
__device__ __align__(16) __nv_bfloat16 g_wlo[8 * DD];

struct Ptr8 { const float* p[8]; };
struct SJobs { const float* W[5]; const float* bias[5]; float* C[5]; };

// ---------------------------------------------------------------------------
// Embedding: e fp32 + split bf16
// ---------------------------------------------------------------------------
__global__ void embed_split(const int* __restrict__ tokens,
                            const float* __restrict__ emb,
                            float* __restrict__ e,
                            __nv_bfloat16* __restrict__ hi,
                            __nv_bfloat16* __restrict__ lo) {
    int idx = blockIdx.x * 256 + threadIdx.x;
    int row = idx / D;
    int d   = idx - row * D;
    float v = emb[tokens[row] * D + d];
    e[idx] = v;
    __nv_bfloat16 hv = __float2bfloat16_rn(v);
    hi[idx] = hv;
    lo[idx] = __float2bfloat16_rn(v - __bfloat162float(hv));
}

// s[b,d] = mean_l e[b,l,d]
__global__ void smean_kernel(const float* __restrict__ e, float* __restrict__ s) {
    __shared__ float red[256];
    int b     = blockIdx.x >> 3;
    int dbase = (blockIdx.x & 7) * 64;
    int tid   = threadIdx.x;
    int d     = dbase + (tid & 63);
    int grp   = tid >> 6;
    const float* p = e + ((b << 9) + grp * 128) * D + d;
    float acc = 0.f;
    #pragma unroll 8
    for (int l = 0; l < 128; l++) acc += p[l * D];
    red[tid] = acc;
    __syncthreads();
    if (tid < 128) red[tid] += red[tid + 128];
    __syncthreads();
    if (tid < 64)
        s[b * D + d] = (red[tid] + red[tid + 64]) * (1.f / (float)L);
}

// ---------------------------------------------------------------------------
// Weight prep: split + transpose all 8 weights; concat biases
// ---------------------------------------------------------------------------
__global__ void wsplit_all(Ptr8 W, __nv_bfloat16* __restrict__ hi,
                           __nv_bfloat16* __restrict__ lo) {
    __shared__ float t[32][33];
    const float* Wsrc = W.p[blockIdx.z];
    __nv_bfloat16* hz = hi + blockIdx.z * DD;
    __nv_bfloat16* lz = lo + blockIdx.z * DD;
    int bx = blockIdx.x, by = blockIdx.y;
    int x = threadIdx.x, y = threadIdx.y;
    #pragma unroll
    for (int j = 0; j < 32; j += 8)
        t[y + j][x] = Wsrc[(by * 32 + y + j) * 512 + bx * 32 + x];
    __syncthreads();
    #pragma unroll
    for (int j = 0; j < 32; j += 8) {
        float v = t[x][y + j];
        int n = bx * 32 + y + j;
        int k = by * 32 + x;
        __nv_bfloat16 hv = __float2bfloat16_rn(v);
        hz[n * 512 + k] = hv;
        lz[n * 512 + k] = __float2bfloat16_rn(v - __bfloat162float(hv));
    }
}

__global__ void biascat(Ptr8 bsrc, float* __restrict__ dst) {
    int i = blockIdx.x * 256 + threadIdx.x;
    dst[i] = bsrc.p[i >> 9][i & 511];
}

// ---------------------------------------------------------------------------
// Tensor-core GEMM: C[8192,N] = A[8192,512] @ Wt[N,512]^T + bias
// 3-term bf16 split; ldmatrix; 128x128x32 tiles, 2-stage cp.async,
// single sync per K-iter, warp phase stagger, term-major MMA order
// (same-accumulator RAW chains spaced by 4 independent MMAs).
// ---------------------------------------------------------------------------
#define SMEM_STAGE 20480
#define SMEM_BYTES (2 * SMEM_STAGE * 2)

__device__ __forceinline__ void mma16816(float* d, const uint32_t* a,
                                         const uint32_t* b) {
    asm volatile("mma.sync.aligned.m16n8k16.row.col.f32.bf16.bf16.f32 "
                 "{%0,%1,%2,%3}, {%4,%5,%6,%7}, {%8,%9}, {%0,%1,%2,%3};"
                 : "+f"(d[0]), "+f"(d[1]), "+f"(d[2]), "+f"(d[3])
                 : "r"(a[0]), "r"(a[1]), "r"(a[2]), "r"(a[3]),
                   "r"(b[0]), "r"(b[1]));
}

__device__ __forceinline__ void ldsm_x4(uint32_t* r, uint32_t a) {
    asm volatile("ldmatrix.sync.aligned.m8n8.x4.shared.b16 {%0,%1,%2,%3}, [%4];"
                 : "=r"(r[0]), "=r"(r[1]), "=r"(r[2]), "=r"(r[3]) : "r"(a));
}

__global__ void __launch_bounds__(256, 2)
mma_gemm(const __nv_bfloat16* __restrict__ Ahi, const __nv_bfloat16* __restrict__ Alo,
         const __nv_bfloat16* __restrict__ Whi, const __nv_bfloat16* __restrict__ Wlo,
         const float* __restrict__ bias, float* __restrict__ C, int ldc) {
    extern __shared__ __nv_bfloat16 sm[];
    const int tid  = threadIdx.x;
    const int lane = tid & 31;
    const int warp = tid >> 5;
    const int wm = warp >> 2;
    const int wn = warp & 3;
    const int m0 = blockIdx.y * 128;
    const int n0 = blockIdx.x * 128;
    const int sks = warp & 1;

    float acc[4][4][4];
    #pragma unroll
    for (int i = 0; i < 4; i++)
        #pragma unroll
        for (int j = 0; j < 4; j++)
            #pragma unroll
            for (int t = 0; t < 4; t++) acc[i][j][t] = 0.f;

    uint32_t smbase = (uint32_t)__cvta_generic_to_shared(sm);

    auto load_stage = [&](int s, int k0) {
        uint32_t base = smbase + (uint32_t)(s * SMEM_STAGE * 2);
        #pragma unroll
        for (int i = 0; i < 2; i++) {
            int id  = tid + i * 256;
            int row = id >> 2;
            int qc  = (id & 3) << 3;
            uint32_t so = base + (uint32_t)((row * 40 + qc) * 2);
            const __nv_bfloat16* ga = Ahi + (m0 + row) * 512 + k0 + qc;
            const __nv_bfloat16* gb = Alo + (m0 + row) * 512 + k0 + qc;
            const __nv_bfloat16* gc = Whi + (n0 + row) * 512 + k0 + qc;
            const __nv_bfloat16* gd = Wlo + (n0 + row) * 512 + k0 + qc;
            asm volatile("cp.async.cg.shared.global [%0], [%1], 16;" :: "r"(so),           "l"(ga));
            asm volatile("cp.async.cg.shared.global [%0], [%1], 16;" :: "r"(so + 10240u), "l"(gb));
            asm volatile("cp.async.cg.shared.global [%0], [%1], 16;" :: "r"(so + 20480u), "l"(gc));
            asm volatile("cp.async.cg.shared.global [%0], [%1], 16;" :: "r"(so + 30720u), "l"(gd));
        }
    };

    load_stage(0, 0);
    asm volatile("cp.async.commit_group;");

    const int lrow  = lane & 15;
    const int lkoff = (lane >> 4) << 3;

    #pragma unroll 1
    for (int it = 0; it < 16; it++) {
        asm volatile("cp.async.wait_group 0;");
        __syncthreads();
        if (it < 15) {
            load_stage((it + 1) & 1, (it + 1) * 32);
            asm volatile("cp.async.commit_group;");
        }

        uint32_t st = smbase + (uint32_t)((it & 1) * SMEM_STAGE * 2);

        #pragma unroll
        for (int s = 0; s < 2; s++) {
            int ks = s ^ sks;
            int col = ks * 16 + lkoff;
            uint32_t bh[4][2], bl[4][2];
            #pragma unroll
            for (int ntp = 0; ntp < 2; ntp++) {
                int n = wn * 32 + ntp * 16 + lrow;
                uint32_t adr = st + 20480u + (uint32_t)((n * 40 + col) * 2);
                uint32_t t4[4];
                ldsm_x4(t4, adr);
                bh[ntp * 2 + 0][0] = t4[0]; bh[ntp * 2 + 0][1] = t4[2];
                bh[ntp * 2 + 1][0] = t4[1]; bh[ntp * 2 + 1][1] = t4[3];
                ldsm_x4(t4, adr + 10240u);
                bl[ntp * 2 + 0][0] = t4[0]; bl[ntp * 2 + 0][1] = t4[2];
                bl[ntp * 2 + 1][0] = t4[1]; bl[ntp * 2 + 1][1] = t4[3];
            }
            #pragma unroll
            for (int mt = 0; mt < 4; mt++) {
                int row = wm * 64 + mt * 16 + lrow;
                uint32_t adr = st + (uint32_t)((row * 40 + col) * 2);
                uint32_t ah[4], al[4];
                ldsm_x4(ah, adr);
                ldsm_x4(al, adr + 10240u);
                // term-major: same-acc RAW chains spaced by 4 independent MMAs
                #pragma unroll
                for (int nt = 0; nt < 4; nt++) mma16816(acc[mt][nt], ah, bh[nt]);
                #pragma unroll
                for (int nt = 0; nt < 4; nt++) mma16816(acc[mt][nt], ah, bl[nt]);
                #pragma unroll
                for (int nt = 0; nt < 4; nt++) mma16816(acc[mt][nt], al, bh[nt]);
            }
        }
    }

    const int r = lane >> 2;
    const int c = (lane & 3) << 1;
    #pragma unroll
    for (int mt = 0; mt < 4; mt++) {
        #pragma unroll
        for (int nt = 0; nt < 4; nt++) {
            int row = m0 + wm * 64 + mt * 16 + r;
            int col = n0 + wn * 32 + nt * 8 + c;
            float b0 = bias[col], b1 = bias[col + 1];
            float2 v0 = make_float2(acc[mt][nt][0] + b0, acc[mt][nt][1] + b1);
            float2 v1 = make_float2(acc[mt][nt][2] + b0, acc[mt][nt][3] + b1);
            *(float2*)(C + row * ldc + col)       = v0;
            *(float2*)(C + (row + 8) * ldc + col) = v1;
        }
    }
}

// ---------------------------------------------------------------------------
// Small GEMM, K-split 2-phase (deterministic); up to 5 jobs per launch
// ---------------------------------------------------------------------------
__global__ void __launch_bounds__(256)
sgemm16_part(const float* __restrict__ A, SJobs jobs, float* __restrict__ part) {
    __shared__ float As[16][64];
    int kc  = blockIdx.x;
    int job = blockIdx.y;
    int tid = threadIdx.x;
    for (int i = tid; i < 16 * 64; i += 256) {
        int r = i >> 6, kk = i & 63;
        As[r][kk] = A[r * 512 + kc * 64 + kk];
    }
    __syncthreads();
    const float* W = jobs.W[job] + (size_t)(kc * 64) * 512;
    float acc0[16], acc1[16];
    #pragma unroll
    for (int r = 0; r < 16; r++) { acc0[r] = 0.f; acc1[r] = 0.f; }
    #pragma unroll 4
    for (int kk = 0; kk < 64; kk++) {
        float w0 = W[kk * 512 + tid];
        float w1 = W[kk * 512 + tid + 256];
        #pragma unroll
        for (int r = 0; r < 16; r++) {
            float a = As[r][kk];
            acc0[r] = fmaf(a, w0, acc0[r]);
            acc1[r] = fmaf(a, w1, acc1[r]);
        }
    }
    float* p = part + ((size_t)job * 8 + kc) * (16 * 512);
    #pragma unroll
    for (int r = 0; r < 16; r++) {
        p[r * 512 + tid]       = acc0[r];
        p[r * 512 + tid + 256] = acc1[r];
    }
}

__global__ void __launch_bounds__(256)
sgemm16_red(SJobs jobs, const float* __restrict__ part) {
    int job = blockIdx.y;
    int i   = blockIdx.x * 256 + threadIdx.x;
    int c   = i & 511;
    const float* p = part + (size_t)job * 8 * (16 * 512) + i;
    float v = jobs.bias[job][c];
    #pragma unroll
    for (int kc = 0; kc < 8; kc++) v += p[kc * (16 * 512)];
    jobs.C[job][i] = v;
}

// ---------------------------------------------------------------------------
// sat attention: 5 keys per token
// ---------------------------------------------------------------------------
__global__ void sat_attn(const float* __restrict__ Q,  int ldq,
                         const float* __restrict__ Kh, const float* __restrict__ Vh,
                         int ldkv,
                         const float* __restrict__ Ke, const float* __restrict__ Ve,
                         int ldke,
                         const float* __restrict__ Ks,  const float* __restrict__ Vs,
                         __nv_bfloat16* __restrict__ chi, __nv_bfloat16* __restrict__ clo) {
    int t = blockIdx.x;
    int b = t >> 9;
    int l = t & 511;
    int head = threadIdx.x >> 5;
    int lane = threadIdx.x & 31;
    int d0 = head * HD + lane;
    int r0 = (b << 9) + ((l + 1) & 511);
    int r2 = (b << 9) + (l == 0 ? (L - 1) : 0);

    const float* qp = Q + (size_t)t * ldq + d0;
    float q0 = qp[0], q1 = qp[32];
    const float* kp[5] = { Kh + (size_t)r0 * ldkv + d0, Kh + (size_t)t * ldkv + d0,
                           Kh + (size_t)r2 * ldkv + d0, Ke + (size_t)t * ldke + d0,
                           Ks + b * D + d0 };
    const float* vp[5] = { Vh + (size_t)r0 * ldkv + d0, Vh + (size_t)t * ldkv + d0,
                           Vh + (size_t)r2 * ldkv + d0, Ve + (size_t)t * ldke + d0,
                           Vs + b * D + d0 };
    float sc[5];
    #pragma unroll
    for (int i = 0; i < 5; i++) {
        float p = q0 * kp[i][0] + q1 * kp[i][32];
        #pragma unroll
        for (int o = 16; o > 0; o >>= 1) p += __shfl_xor_sync(0xffffffffu, p, o);
        sc[i] = p * 0.125f;
    }
    float m = sc[0];
    #pragma unroll
    for (int i = 1; i < 5; i++) m = fmaxf(m, sc[i]);
    float den = 0.f;
    #pragma unroll
    for (int i = 0; i < 5; i++) { sc[i] = expf(sc[i] - m); den += sc[i]; }
    float inv = 1.f / den;
    float o0 = 0.f, o1 = 0.f;
    #pragma unroll
    for (int i = 0; i < 5; i++) {
        o0 = fmaf(sc[i], vp[i][0],  o0);
        o1 = fmaf(sc[i], vp[i][32], o1);
    }
    o0 *= inv; o1 *= inv;
    int base = t * D;
    __nv_bfloat16 h0 = __float2bfloat16_rn(o0);
    __nv_bfloat16 h1 = __float2bfloat16_rn(o1);
    chi[base + d0]      = h0;
    chi[base + d0 + 32] = h1;
    clo[base + d0]      = __float2bfloat16_rn(o0 - __bfloat162float(h0));
    clo[base + d0 + 32] = __float2bfloat16_rn(o1 - __bfloat162float(h1));
}

// ---------------------------------------------------------------------------
// rel attention: 513 keys; krvr layout (ld 1024, kr@0, vr@+512).
// ---------------------------------------------------------------------------
__global__ void rel_attn(const float* __restrict__ Qs,  const float* __restrict__ Ksr,
                         const float* __restrict__ KrVr, const float* __restrict__ Vsr,
                         float* __restrict__ ctxs) {
    __shared__ float sc[513];
    __shared__ float red[256];
    __shared__ float qsh[HD];
    int b    = blockIdx.x >> 3;
    int head = blockIdx.x & 7;
    int tid  = threadIdx.x;
    int warp = tid >> 5;
    int lane = tid & 31;
    int off  = head * HD;

    if (tid < HD) qsh[tid] = Qs[b * D + off + tid];
    __syncthreads();

    float q0 = qsh[lane], q1 = qsh[lane + 32];
    for (int k = warp; k < 513; k += 8) {
        const float* kv = (k == 0) ? (Ksr + b * D + off)
                                   : (KrVr + (size_t)((b << 9) + k - 1) * 1024 + off);
        float p = q0 * kv[lane] + q1 * kv[lane + 32];
        #pragma unroll
        for (int o = 16; o > 0; o >>= 1) p += __shfl_xor_sync(0xffffffffu, p, o);
        if (lane == 0) sc[k] = p * 0.125f;
    }
    __syncthreads();

    float m = -1e30f;
    for (int k = tid; k < 513; k += 256) m = fmaxf(m, sc[k]);
    red[tid] = m; __syncthreads();
    for (int st = 128; st > 0; st >>= 1) {
        if (tid < st) red[tid] = fmaxf(red[tid], red[tid + st]);
        __syncthreads();
    }
    m = red[0];
    __syncthreads();

    float dsum = 0.f;
    for (int k = tid; k < 513; k += 256) {
        float e_ = expf(sc[k] - m);
        sc[k] = e_;
        dsum += e_;
    }
    red[tid] = dsum; __syncthreads();
    for (int st = 128; st > 0; st >>= 1) {
        if (tid < st) red[tid] += red[tid + st];
        __syncthreads();
    }
    float inv = 1.f / red[0];
    __syncthreads();

    int d = tid & 63;
    int g = tid >> 6;
    float acc = 0.f;
    for (int k = g; k < 513; k += 4) {
        const float* vv = (k == 0) ? (Vsr + b * D + off)
                                   : (KrVr + (size_t)((b << 9) + k - 1) * 1024 + 512 + off);
        acc = fmaf(sc[k], vv[d], acc);
    }
    red[tid] = acc;
    __syncthreads();
    if (tid < 64) {
        float o = red[tid] + red[tid + 64] + red[tid + 128] + red[tid + 192];
        ctxs[b * D + off + tid] = o * inv;
    }
}

// ---------------------------------------------------------------------------
// relu + LayerNorm (+ optional bf16 split outputs)
// ---------------------------------------------------------------------------
__global__ void relu_ln(const float* __restrict__ x, const float* __restrict__ w,
                        const float* __restrict__ bb, float* __restrict__ out,
                        __nv_bfloat16* __restrict__ hi, __nv_bfloat16* __restrict__ lo) {
    __shared__ float red[256];
    int row = blockIdx.x;
    int tid = threadIdx.x;
    float v0 = fmaxf(x[row * D + tid],       0.f);
    float v1 = fmaxf(x[row * D + tid + 256], 0.f);
    red[tid] = v0 + v1;
    __syncthreads();
    for (int st = 128; st > 0; st >>= 1) {
        if (tid < st) red[tid] += red[tid + st];
        __syncthreads();
    }
    float mean = red[0] * (1.f / 512.f);
    __syncthreads();
    float d0 = v0 - mean, d1 = v1 - mean;
    red[tid] = d0 * d0 + d1 * d1;
    __syncthreads();
    for (int st = 128; st > 0; st >>= 1) {
        if (tid < st) red[tid] += red[tid + st];
        __syncthreads();
    }
    float inv = rsqrtf(red[0] * (1.f / 512.f) + 1e-12f);
    float o0 = w[tid]       * d0 * inv + bb[tid];
    float o1 = w[tid + 256] * d1 * inv + bb[tid + 256];
    out[row * D + tid]       = o0;
    out[row * D + tid + 256] = o1;
    if (hi) {
        __nv_bfloat16 h0 = __float2bfloat16_rn(o0);
        __nv_bfloat16 h1 = __float2bfloat16_rn(o1);
        hi[row * D + tid]       = h0;
        hi[row * D + tid + 256] = h1;
        lo[row * D + tid]       = __float2bfloat16_rn(o0 - __bfloat162float(h0));
        lo[row * D + tid + 256] = __float2bfloat16_rn(o1 - __bfloat162float(h1));
    }
}

// ---------------------------------------------------------------------------
// logits = h @ ofc_w[512,17] + ofc_b
// ---------------------------------------------------------------------------
__global__ void final_logits(const float* __restrict__ h, const float* __restrict__ W,
                             const float* __restrict__ bias, float* __restrict__ out) {
    __shared__ float Wsh[512 * T];
    int tid = threadIdx.x;
    for (int i = tid; i < 512 * T; i += 256) Wsh[i] = W[i];
    __syncthreads();
    int warp = tid >> 5, lane = tid & 31;
    int row = blockIdx.x * 8 + warp;
    float acc[T];
    #pragma unroll
    for (int t = 0; t < T; t++) acc[t] = 0.f;
    const float* hr = h + row * D;
    for (int k = lane; k < D; k += 32) {
        float a = hr[k];
        #pragma unroll
        for (int t = 0; t < T; t++) acc[t] = fmaf(a, Wsh[k * T + t], acc[t]);
    }
    #pragma unroll
    for (int t = 0; t < T; t++)
        #pragma unroll
        for (int o = 16; o > 0; o >>= 1)
            acc[t] += __shfl_xor_sync(0xffffffffu, acc[t], o);
    if (lane == 0) {
        #pragma unroll
        for (int t = 0; t < T; t++) out[row * T + t] = acc[t] + bias[t];
    }
}

// ---------------------------------------------------------------------------
// Launch (two-stream overlap via event fork/join — capture-safe pattern)
// ---------------------------------------------------------------------------
extern "C" void kernel_launch(void* const* d_in, const int* in_sizes, int n_in,
                              void* d_out, int out_size) {
    (void)in_sizes; (void)n_in; (void)out_size;
    const int*   tokens  = (const int*)  d_in[0];
    const float* emb     = (const float*)d_in[4];
    Ptr8 wsrc = {{ (const float*)d_in[5],  (const float*)d_in[7],
                   (const float*)d_in[9],  (const float*)d_in[11],
                   (const float*)d_in[13], (const float*)d_in[15],
                   (const float*)d_in[17], (const float*)d_in[19] }};
    Ptr8 bsrc = {{ (const float*)d_in[6],  (const float*)d_in[8],
                   (const float*)d_in[10], (const float*)d_in[12],
                   (const float*)d_in[14], (const float*)d_in[16],
                   (const float*)d_in[18], (const float*)d_in[20] }};
    const float* sat_kw = (const float*)d_in[7];
    const float* sat_kb = (const float*)d_in[8];
    const float* sat_vw = (const float*)d_in[9];
    const float* sat_vb = (const float*)d_in[10];
    const float* rel_qw = (const float*)d_in[13];
    const float* rel_qb = (const float*)d_in[14];
    const float* rel_kw = (const float*)d_in[15];
    const float* rel_kb = (const float*)d_in[16];
    const float* rel_vw = (const float*)d_in[17];
    const float* rel_vb = (const float*)d_in[18];
    const float* rel_ow = (const float*)d_in[19];
    const float* rel_ob = (const float*)d_in[20];
    const float* ln_sw  = (const float*)d_in[21];
    const float* ln_sb  = (const float*)d_in[22];
    const float* ln_rw  = (const float*)d_in[23];
    const float* ln_rb  = (const float*)d_in[24];
    const float* ofc_w  = (const float*)d_in[25];
    const float* ofc_b  = (const float*)d_in[26];
    float* out = (float*)d_out;

    float *e, *h, *s, *qkv, *qkeve, *krvr, *a;
    float *ks, *vs, *qsr, *ksr, *vsr, *ctxs, *r, *bias, *part;
    __nv_bfloat16 *ehi, *elo, *hhi, *hlo, *cthi, *ctlo, *whi, *wlo;
    cudaGetSymbolAddress((void**)&e,     g_e);
    cudaGetSymbolAddress((void**)&h,     g_h);
    cudaGetSymbolAddress((void**)&s,     g_s);
    cudaGetSymbolAddress((void**)&qkv,   g_qkv);
    cudaGetSymbolAddress((void**)&qkeve, g_qkeve);
    cudaGetSymbolAddress((void**)&krvr,  g_krvr);
    cudaGetSymbolAddress((void**)&a,     g_a);
    cudaGetSymbolAddress((void**)&ks,    g_ks);
    cudaGetSymbolAddress((void**)&vs,    g_vs);
    cudaGetSymbolAddress((void**)&qsr,   g_qsr);
    cudaGetSymbolAddress((void**)&ksr,   g_ksr);
    cudaGetSymbolAddress((void**)&vsr,   g_vsr);
    cudaGetSymbolAddress((void**)&ctxs,  g_ctxs);
    cudaGetSymbolAddress((void**)&r,     g_r);
    cudaGetSymbolAddress((void**)&bias,  g_bias);
    cudaGetSymbolAddress((void**)&part,  g_part);
    cudaGetSymbolAddress((void**)&ehi,   g_ehi);
    cudaGetSymbolAddress((void**)&elo,   g_elo);
    cudaGetSymbolAddress((void**)&hhi,   g_hhi);
    cudaGetSymbolAddress((void**)&hlo,   g_hlo);
    cudaGetSymbolAddress((void**)&cthi,  g_cthi);
    cudaGetSymbolAddress((void**)&ctlo,  g_ctlo);
    cudaGetSymbolAddress((void**)&whi,   g_whi);
    cudaGetSymbolAddress((void**)&wlo,   g_wlo);

    cudaFuncSetAttribute(mma_gemm, cudaFuncAttributeMaxDynamicSharedMemorySize,
                         SMEM_BYTES);

    cudaStream_t s2;
    cudaStreamCreateWithFlags(&s2, cudaStreamNonBlocking);
    cudaEvent_t evA, evB, evC, evD;
    cudaEventCreateWithFlags(&evA, cudaEventDisableTiming);
    cudaEventCreateWithFlags(&evB, cudaEventDisableTiming);
    cudaEventCreateWithFlags(&evC, cudaEventDisableTiming);
    cudaEventCreateWithFlags(&evD, cudaEventDisableTiming);

    #define GEMM(AHI, ALO, WI, NTOT, OUT, LDC, STRM)                           \
        mma_gemm<<<dim3((NTOT) / 128, 64), 256, SMEM_BYTES, STRM>>>(           \
            AHI, ALO, whi + (WI) * DD, wlo + (WI) * DD, bias + (WI) * 512,     \
            OUT, LDC)

    #define SMALL(AIN, JOBS, NJ, STRM)                                         \
        do {                                                                   \
            sgemm16_part<<<dim3(8, NJ), 256, 0, STRM>>>(AIN, JOBS, part);      \
            sgemm16_red<<<dim3(32, NJ), 256, 0, STRM>>>(JOBS, part);           \
        } while (0)

    // Prologue (stream 0)
    wsplit_all<<<dim3(16, 16, 8), dim3(32, 8)>>>(wsrc, whi, wlo);
    biascat<<<16, 256>>>(bsrc, bias);
    embed_split<<<BL * D / 256, 256>>>(tokens, emb, e, ehi, elo);
    cudaEventRecord(evA, 0);

    // Stream 0: cycle-0 fused e-projection q | ke | ve (slots 0-2)
    GEMM(ehi, elo, 0, 1536, qkeve, 1536, 0);

    // Stream 2 (forked after embed): smean + all 5 s-projections
    cudaStreamWaitEvent(s2, evA, 0);
    smean_kernel<<<B * 8, 256, 0, s2>>>(e, s);
    {
        SJobs j = {{ sat_kw, sat_vw, rel_qw, rel_kw, rel_vw },
                   { sat_kb, sat_vb, rel_qb, rel_kb, rel_vb },
                   { ks, vs, qsr, ksr, vsr }};
        SMALL(s, j, 5, s2);
    }
    cudaEventRecord(evB, s2);
    cudaStreamWaitEvent(0, evB, 0);   // join before sat_attn

    // ---- cycle 0 (stream 0) ----
    sat_attn<<<BL, 256>>>(qkeve, 1536,
                          qkeve + 512, qkeve + 1024, 1536,
                          qkeve + 512, qkeve + 1024, 1536,
                          ks, vs, cthi, ctlo);
    GEMM(cthi, ctlo, 3, 512, a, 512, 0);           // sat_o
    relu_ln<<<BL, 256>>>(a, ln_sw, ln_sb, h, hhi, hlo);
    cudaEventRecord(evC, 0);

    // Stream 2: cycle-1 qkv GEMM (depends only on h split)
    cudaStreamWaitEvent(s2, evC, 0);
    GEMM(hhi, hlo, 0, 1536, qkv, 1536, s2);

    // Stream 0 (concurrent): rel chain
    GEMM(hhi, hlo, 5, 1024, krvr, 1024, 0);        // rel_k | rel_v
    rel_attn<<<B * NH, 256>>>(qsr, ksr, krvr, vsr, ctxs);
    {
        SJobs j = {{ rel_ow, nullptr, nullptr, nullptr, nullptr },
                   { rel_ob, nullptr, nullptr, nullptr, nullptr },
                   { r, nullptr, nullptr, nullptr, nullptr }};
        SMALL(ctxs, j, 1, 0);
    }
    relu_ln<<<B, 256>>>(r, ln_rw, ln_rb, s, nullptr, nullptr);
    {
        SJobs j = {{ sat_kw, sat_vw, nullptr, nullptr, nullptr },
                   { sat_kb, sat_vb, nullptr, nullptr, nullptr },
                   { ks, vs, nullptr, nullptr, nullptr }};
        SMALL(s, j, 2, 0);
    }
    cudaEventRecord(evD, s2);
    cudaStreamWaitEvent(0, evD, 0);   // join: sat_attn needs qkv

    // ---- cycle 1 (stream 0; rel path dead) ----
    sat_attn<<<BL, 256>>>(qkv, 1536,
                          qkv + 512, qkv + 1024, 1536,
                          qkeve + 512, qkeve + 1024, 1536,
                          ks, vs, cthi, ctlo);
    GEMM(cthi, ctlo, 3, 512, a, 512, 0);           // sat_o
    relu_ln<<<BL, 256>>>(a, ln_sw, ln_sb, h, nullptr, nullptr);

    final_logits<<<BL / 8, 256>>>(h, ofc_w, ofc_b, out);

    cudaEventDestroy(evA);
    cudaEventDestroy(evB);
    cudaEventDestroy(evC);
    cudaEventDestroy(evD);
    cudaStreamDestroy(s2);
}

// round 16
// speedup vs baseline: 1.6329x; 1.0366x over previous
#include <cuda_runtime.h>
#include <cuda_bf16.h>
#include <cstdint>
#include <math.h>

// Problem constants
#define B   16
#define L   512
#define D   512
#define NH  8
#define HD  64
#define T   17
#define CYC 2
#define BL  (B * L)   // 8192
#define DD  (D * D)

// Weight slots (transposed buffer): 0 sat_q, 1 sat_k, 2 sat_v, 3 sat_o,
//                                   4 rel_q, 5 rel_k, 6 rel_v, 7 rel_o
// ---------------------------------------------------------------------------
// Scratch (device globals)
// ---------------------------------------------------------------------------
__device__ float g_s[B * D];
__device__ float g_qkv[BL * 1536];    // cyc1: q | k | v
__device__ float g_qkeve[BL * 1536];  // cyc0: q | ke | ve
__device__ float g_krvr[BL * 1024];   // kr | vr
__device__ float g_a[BL * D];
__device__ float g_ks[B * D];
__device__ float g_vs[B * D];
__device__ float g_qsr[B * D];
__device__ float g_ksr[B * D];
__device__ float g_vsr[B * D];
__device__ float g_ctxs[B * D];
__device__ float g_r[B * D];
__device__ float g_bias[8 * D];
__device__ float g_part[5 * 8 * 16 * 512];   // small-gemm K-split partials
__device__ float g_h[BL * D];

// bf16 split buffers (16B aligned for cp.async 16)
__device__ __align__(16) __nv_bfloat16 g_ehi[BL * D];
__device__ __align__(16) __nv_bfloat16 g_elo[BL * D];
__device__ __align__(16) __nv_bfloat16 g_hhi[BL * D];
__device__ __align__(16) __nv_bfloat16 g_hlo[BL * D];
__device__ __align__(16) __nv_bfloat16 g_cthi[BL * D];
__device__ __align__(16) __nv_bfloat16 g_ctlo[BL * D];
__device__ __align__(16) __nv_bfloat16 g_whi[8 * DD];   // transposed [N][K]
__device__ __align__(16) __nv_bfloat16 g_wlo[8 * DD];

struct Ptr8 { const float* p[8]; };
struct SJobs { const float* W[5]; const float* bias[5]; float* C[5]; };

// ---------------------------------------------------------------------------
// Embedding: split bf16 only
// ---------------------------------------------------------------------------
__global__ void embed_split(const int* __restrict__ tokens,
                            const float* __restrict__ emb,
                            __nv_bfloat16* __restrict__ hi,
                            __nv_bfloat16* __restrict__ lo) {
    int idx = blockIdx.x * 256 + threadIdx.x;
    int row = idx / D;
    int d   = idx - row * D;
    float v = emb[tokens[row] * D + d];
    __nv_bfloat16 hv = __float2bfloat16_rn(v);
    hi[idx] = hv;
    lo[idx] = __float2bfloat16_rn(v - __bfloat162float(hv));
}

// s[b,d] = mean_l (hi+lo)[b,l,d]
__global__ void smean_kernel(const __nv_bfloat16* __restrict__ hi,
                             const __nv_bfloat16* __restrict__ lo,
                             float* __restrict__ s) {
    __shared__ float red[256];
    int b     = blockIdx.x >> 3;
    int dbase = (blockIdx.x & 7) * 64;
    int tid   = threadIdx.x;
    int d     = dbase + (tid & 63);
    int grp   = tid >> 6;
    size_t base = (size_t)((b << 9) + grp * 128) * D + d;
    float acc = 0.f;
    #pragma unroll 8
    for (int l = 0; l < 128; l++) {
        size_t ix = base + (size_t)l * D;
        acc += __bfloat162float(hi[ix]) + __bfloat162float(lo[ix]);
    }
    red[tid] = acc;
    __syncthreads();
    if (tid < 128) red[tid] += red[tid + 128];
    __syncthreads();
    if (tid < 64)
        s[b * D + d] = (red[tid] + red[tid + 64]) * (1.f / (float)L);
}

// ---------------------------------------------------------------------------
// Weight prep: split + transpose all 8 weights; concat biases
// ---------------------------------------------------------------------------
__global__ void wsplit_all(Ptr8 W, __nv_bfloat16* __restrict__ hi,
                           __nv_bfloat16* __restrict__ lo) {
    __shared__ float t[32][33];
    const float* Wsrc = W.p[blockIdx.z];
    __nv_bfloat16* hz = hi + blockIdx.z * DD;
    __nv_bfloat16* lz = lo + blockIdx.z * DD;
    int bx = blockIdx.x, by = blockIdx.y;
    int x = threadIdx.x, y = threadIdx.y;
    #pragma unroll
    for (int j = 0; j < 32; j += 8)
        t[y + j][x] = Wsrc[(by * 32 + y + j) * 512 + bx * 32 + x];
    __syncthreads();
    #pragma unroll
    for (int j = 0; j < 32; j += 8) {
        float v = t[x][y + j];
        int n = bx * 32 + y + j;
        int k = by * 32 + x;
        __nv_bfloat16 hv = __float2bfloat16_rn(v);
        hz[n * 512 + k] = hv;
        lz[n * 512 + k] = __float2bfloat16_rn(v - __bfloat162float(hv));
    }
}

__global__ void biascat(Ptr8 bsrc, float* __restrict__ dst) {
    int i = blockIdx.x * 256 + threadIdx.x;
    dst[i] = bsrc.p[i >> 9][i & 511];
}

// ---------------------------------------------------------------------------
// Tensor-core GEMM: C[8192,N] = A[8192,512] @ Wt[N,512]^T + bias
// ---------------------------------------------------------------------------
#define SMEM_STAGE 20480
#define SMEM_BYTES (2 * SMEM_STAGE * 2)

__device__ __forceinline__ void mma16816(float* d, const uint32_t* a,
                                         const uint32_t* b) {
    asm volatile("mma.sync.aligned.m16n8k16.row.col.f32.bf16.bf16.f32 "
                 "{%0,%1,%2,%3}, {%4,%5,%6,%7}, {%8,%9}, {%0,%1,%2,%3};"
                 : "+f"(d[0]), "+f"(d[1]), "+f"(d[2]), "+f"(d[3])
                 : "r"(a[0]), "r"(a[1]), "r"(a[2]), "r"(a[3]),
                   "r"(b[0]), "r"(b[1]));
}

__device__ __forceinline__ void ldsm_x4(uint32_t* r, uint32_t a) {
    asm volatile("ldmatrix.sync.aligned.m8n8.x4.shared.b16 {%0,%1,%2,%3}, [%4];"
                 : "=r"(r[0]), "=r"(r[1]), "=r"(r[2]), "=r"(r[3]) : "r"(a));
}

__global__ void __launch_bounds__(256, 2)
mma_gemm(const __nv_bfloat16* __restrict__ Ahi, const __nv_bfloat16* __restrict__ Alo,
         const __nv_bfloat16* __restrict__ Whi, const __nv_bfloat16* __restrict__ Wlo,
         const float* __restrict__ bias, float* __restrict__ C, int ldc) {
    extern __shared__ __nv_bfloat16 sm[];
    const int tid  = threadIdx.x;
    const int lane = tid & 31;
    const int warp = tid >> 5;
    const int wm = warp >> 2;
    const int wn = warp & 3;
    const int m0 = blockIdx.y * 128;
    const int n0 = blockIdx.x * 128;
    const int sks = warp & 1;

    float acc[4][4][4];
    #pragma unroll
    for (int i = 0; i < 4; i++)
        #pragma unroll
        for (int j = 0; j < 4; j++)
            #pragma unroll
            for (int t = 0; t < 4; t++) acc[i][j][t] = 0.f;

    uint32_t smbase = (uint32_t)__cvta_generic_to_shared(sm);

    auto load_stage = [&](int s, int k0) {
        uint32_t base = smbase + (uint32_t)(s * SMEM_STAGE * 2);
        #pragma unroll
        for (int i = 0; i < 2; i++) {
            int id  = tid + i * 256;
            int row = id >> 2;
            int qc  = (id & 3) << 3;
            uint32_t so = base + (uint32_t)((row * 40 + qc) * 2);
            const __nv_bfloat16* ga = Ahi + (m0 + row) * 512 + k0 + qc;
            const __nv_bfloat16* gb = Alo + (m0 + row) * 512 + k0 + qc;
            const __nv_bfloat16* gc = Whi + (n0 + row) * 512 + k0 + qc;
            const __nv_bfloat16* gd = Wlo + (n0 + row) * 512 + k0 + qc;
            asm volatile("cp.async.cg.shared.global [%0], [%1], 16;" :: "r"(so),           "l"(ga));
            asm volatile("cp.async.cg.shared.global [%0], [%1], 16;" :: "r"(so + 10240u), "l"(gb));
            asm volatile("cp.async.cg.shared.global [%0], [%1], 16;" :: "r"(so + 20480u), "l"(gc));
            asm volatile("cp.async.cg.shared.global [%0], [%1], 16;" :: "r"(so + 30720u), "l"(gd));
        }
    };

    load_stage(0, 0);
    asm volatile("cp.async.commit_group;");

    const int lrow  = lane & 15;
    const int lkoff = (lane >> 4) << 3;

    #pragma unroll 1
    for (int it = 0; it < 16; it++) {
        asm volatile("cp.async.wait_group 0;");
        __syncthreads();
        if (it < 15) {
            load_stage((it + 1) & 1, (it + 1) * 32);
            asm volatile("cp.async.commit_group;");
        }

        uint32_t st = smbase + (uint32_t)((it & 1) * SMEM_STAGE * 2);

        #pragma unroll
        for (int s = 0; s < 2; s++) {
            int ks = s ^ sks;
            int col = ks * 16 + lkoff;
            uint32_t bh[4][2], bl[4][2];
            #pragma unroll
            for (int ntp = 0; ntp < 2; ntp++) {
                int n = wn * 32 + ntp * 16 + lrow;
                uint32_t adr = st + 20480u + (uint32_t)((n * 40 + col) * 2);
                uint32_t t4[4];
                ldsm_x4(t4, adr);
                bh[ntp * 2 + 0][0] = t4[0]; bh[ntp * 2 + 0][1] = t4[2];
                bh[ntp * 2 + 1][0] = t4[1]; bh[ntp * 2 + 1][1] = t4[3];
                ldsm_x4(t4, adr + 10240u);
                bl[ntp * 2 + 0][0] = t4[0]; bl[ntp * 2 + 0][1] = t4[2];
                bl[ntp * 2 + 1][0] = t4[1]; bl[ntp * 2 + 1][1] = t4[3];
            }
            #pragma unroll
            for (int mt = 0; mt < 4; mt++) {
                int row = wm * 64 + mt * 16 + lrow;
                uint32_t adr = st + (uint32_t)((row * 40 + col) * 2);
                uint32_t ah[4], al[4];
                ldsm_x4(ah, adr);
                ldsm_x4(al, adr + 10240u);
                #pragma unroll
                for (int nt = 0; nt < 4; nt++) {
                    mma16816(acc[mt][nt], ah, bh[nt]);
                    mma16816(acc[mt][nt], ah, bl[nt]);
                    mma16816(acc[mt][nt], al, bh[nt]);
                }
            }
        }
    }

    const int r = lane >> 2;
    const int c = (lane & 3) << 1;
    #pragma unroll
    for (int mt = 0; mt < 4; mt++) {
        #pragma unroll
        for (int nt = 0; nt < 4; nt++) {
            int row = m0 + wm * 64 + mt * 16 + r;
            int col = n0 + wn * 32 + nt * 8 + c;
            float b0 = bias[col], b1 = bias[col + 1];
            float2 v0 = make_float2(acc[mt][nt][0] + b0, acc[mt][nt][1] + b1);
            float2 v1 = make_float2(acc[mt][nt][2] + b0, acc[mt][nt][3] + b1);
            *(float2*)(C + row * ldc + col)       = v0;
            *(float2*)(C + (row + 8) * ldc + col) = v1;
        }
    }
}

// ---------------------------------------------------------------------------
// Small GEMM, K-split 2-phase; up to 5 jobs per launch
// ---------------------------------------------------------------------------
__global__ void __launch_bounds__(256)
sgemm16_part(const float* __restrict__ A, SJobs jobs, float* __restrict__ part) {
    __shared__ float As[16][64];
    int kc  = blockIdx.x;
    int job = blockIdx.y;
    int tid = threadIdx.x;
    for (int i = tid; i < 16 * 64; i += 256) {
        int r = i >> 6, kk = i & 63;
        As[r][kk] = A[r * 512 + kc * 64 + kk];
    }
    __syncthreads();
    const float* W = jobs.W[job] + (size_t)(kc * 64) * 512;
    float acc0[16], acc1[16];
    #pragma unroll
    for (int r = 0; r < 16; r++) { acc0[r] = 0.f; acc1[r] = 0.f; }
    #pragma unroll 4
    for (int kk = 0; kk < 64; kk++) {
        float w0 = W[kk * 512 + tid];
        float w1 = W[kk * 512 + tid + 256];
        #pragma unroll
        for (int r = 0; r < 16; r++) {
            float a = As[r][kk];
            acc0[r] = fmaf(a, w0, acc0[r]);
            acc1[r] = fmaf(a, w1, acc1[r]);
        }
    }
    float* p = part + ((size_t)job * 8 + kc) * (16 * 512);
    #pragma unroll
    for (int r = 0; r < 16; r++) {
        p[r * 512 + tid]       = acc0[r];
        p[r * 512 + tid + 256] = acc1[r];
    }
}

__global__ void __launch_bounds__(256)
sgemm16_red(SJobs jobs, const float* __restrict__ part) {
    int job = blockIdx.y;
    int i   = blockIdx.x * 256 + threadIdx.x;
    int c   = i & 511;
    const float* p = part + (size_t)job * 8 * (16 * 512) + i;
    float v = jobs.bias[job][c];
    #pragma unroll
    for (int kc = 0; kc < 8; kc++) v += p[kc * (16 * 512)];
    jobs.C[job][i] = v;
}

// ---------------------------------------------------------------------------
// sat attention: 5 keys per token
// ---------------------------------------------------------------------------
__global__ void sat_attn(const float* __restrict__ Q,  int ldq,
                         const float* __restrict__ Kh, const float* __restrict__ Vh,
                         int ldkv,
                         const float* __restrict__ Ke, const float* __restrict__ Ve,
                         int ldke,
                         const float* __restrict__ Ks,  const float* __restrict__ Vs,
                         __nv_bfloat16* __restrict__ chi, __nv_bfloat16* __restrict__ clo) {
    int t = blockIdx.x;
    int b = t >> 9;
    int l = t & 511;
    int head = threadIdx.x >> 5;
    int lane = threadIdx.x & 31;
    int d0 = head * HD + lane;
    int r0 = (b << 9) + ((l + 1) & 511);
    int r2 = (b << 9) + (l == 0 ? (L - 1) : 0);

    const float* qp = Q + (size_t)t * ldq + d0;
    float q0 = qp[0], q1 = qp[32];
    const float* kp[5] = { Kh + (size_t)r0 * ldkv + d0, Kh + (size_t)t * ldkv + d0,
                           Kh + (size_t)r2 * ldkv + d0, Ke + (size_t)t * ldke + d0,
                           Ks + b * D + d0 };
    const float* vp[5] = { Vh + (size_t)r0 * ldkv + d0, Vh + (size_t)t * ldkv + d0,
                           Vh + (size_t)r2 * ldkv + d0, Ve + (size_t)t * ldke + d0,
                           Vs + b * D + d0 };
    float sc[5];
    #pragma unroll
    for (int i = 0; i < 5; i++) {
        float p = q0 * kp[i][0] + q1 * kp[i][32];
        #pragma unroll
        for (int o = 16; o > 0; o >>= 1) p += __shfl_xor_sync(0xffffffffu, p, o);
        sc[i] = p * 0.125f;
    }
    float m = sc[0];
    #pragma unroll
    for (int i = 1; i < 5; i++) m = fmaxf(m, sc[i]);
    float den = 0.f;
    #pragma unroll
    for (int i = 0; i < 5; i++) { sc[i] = expf(sc[i] - m); den += sc[i]; }
    float inv = 1.f / den;
    float o0 = 0.f, o1 = 0.f;
    #pragma unroll
    for (int i = 0; i < 5; i++) {
        o0 = fmaf(sc[i], vp[i][0],  o0);
        o1 = fmaf(sc[i], vp[i][32], o1);
    }
    o0 *= inv; o1 *= inv;
    int base = t * D;
    __nv_bfloat16 h0 = __float2bfloat16_rn(o0);
    __nv_bfloat16 h1 = __float2bfloat16_rn(o1);
    chi[base + d0]      = h0;
    chi[base + d0 + 32] = h1;
    clo[base + d0]      = __float2bfloat16_rn(o0 - __bfloat162float(h0));
    clo[base + d0 + 32] = __float2bfloat16_rn(o1 - __bfloat162float(h1));
}

// ---------------------------------------------------------------------------
// rel attention: 513 keys; krvr layout (ld 1024, kr@0, vr@+512).
// ---------------------------------------------------------------------------
__global__ void rel_attn(const float* __restrict__ Qs,  const float* __restrict__ Ksr,
                         const float* __restrict__ KrVr, const float* __restrict__ Vsr,
                         float* __restrict__ ctxs) {
    __shared__ float sc[513];
    __shared__ float red[256];
    __shared__ float qsh[HD];
    int b    = blockIdx.x >> 3;
    int head = blockIdx.x & 7;
    int tid  = threadIdx.x;
    int warp = tid >> 5;
    int lane = tid & 31;
    int off  = head * HD;

    if (tid < HD) qsh[tid] = Qs[b * D + off + tid];
    __syncthreads();

    float q0 = qsh[lane], q1 = qsh[lane + 32];
    for (int k = warp; k < 513; k += 8) {
        const float* kv = (k == 0) ? (Ksr + b * D + off)
                                   : (KrVr + (size_t)((b << 9) + k - 1) * 1024 + off);
        float p = q0 * kv[lane] + q1 * kv[lane + 32];
        #pragma unroll
        for (int o = 16; o > 0; o >>= 1) p += __shfl_xor_sync(0xffffffffu, p, o);
        if (lane == 0) sc[k] = p * 0.125f;
    }
    __syncthreads();

    float m = -1e30f;
    for (int k = tid; k < 513; k += 256) m = fmaxf(m, sc[k]);
    red[tid] = m; __syncthreads();
    for (int st = 128; st > 0; st >>= 1) {
        if (tid < st) red[tid] = fmaxf(red[tid], red[tid + st]);
        __syncthreads();
    }
    m = red[0];
    __syncthreads();

    float dsum = 0.f;
    for (int k = tid; k < 513; k += 256) {
        float e_ = expf(sc[k] - m);
        sc[k] = e_;
        dsum += e_;
    }
    red[tid] = dsum; __syncthreads();
    for (int st = 128; st > 0; st >>= 1) {
        if (tid < st) red[tid] += red[tid + st];
        __syncthreads();
    }
    float inv = 1.f / red[0];
    __syncthreads();

    int d = tid & 63;
    int g = tid >> 6;
    float acc = 0.f;
    for (int k = g; k < 513; k += 4) {
        const float* vv = (k == 0) ? (Vsr + b * D + off)
                                   : (KrVr + (size_t)((b << 9) + k - 1) * 1024 + 512 + off);
        acc = fmaf(sc[k], vv[d], acc);
    }
    red[tid] = acc;
    __syncthreads();
    if (tid < 64) {
        float o = red[tid] + red[tid + 64] + red[tid + 128] + red[tid + 192];
        ctxs[b * D + off + tid] = o * inv;
    }
}

// ---------------------------------------------------------------------------
// relu + LayerNorm (+ optional bf16 split outputs)
// ---------------------------------------------------------------------------
__global__ void relu_ln(const float* __restrict__ x, const float* __restrict__ w,
                        const float* __restrict__ bb, float* __restrict__ out,
                        __nv_bfloat16* __restrict__ hi, __nv_bfloat16* __restrict__ lo) {
    __shared__ float red[256];
    int row = blockIdx.x;
    int tid = threadIdx.x;
    float v0 = fmaxf(x[row * D + tid],       0.f);
    float v1 = fmaxf(x[row * D + tid + 256], 0.f);
    red[tid] = v0 + v1;
    __syncthreads();
    for (int st = 128; st > 0; st >>= 1) {
        if (tid < st) red[tid] += red[tid + st];
        __syncthreads();
    }
    float mean = red[0] * (1.f / 512.f);
    __syncthreads();
    float d0 = v0 - mean, d1 = v1 - mean;
    red[tid] = d0 * d0 + d1 * d1;
    __syncthreads();
    for (int st = 128; st > 0; st >>= 1) {
        if (tid < st) red[tid] += red[tid + st];
        __syncthreads();
    }
    float inv = rsqrtf(red[0] * (1.f / 512.f) + 1e-12f);
    float o0 = w[tid]       * d0 * inv + bb[tid];
    float o1 = w[tid + 256] * d1 * inv + bb[tid + 256];
    out[row * D + tid]       = o0;
    out[row * D + tid + 256] = o1;
    if (hi) {
        __nv_bfloat16 h0 = __float2bfloat16_rn(o0);
        __nv_bfloat16 h1 = __float2bfloat16_rn(o1);
        hi[row * D + tid]       = h0;
        hi[row * D + tid + 256] = h1;
        lo[row * D + tid]       = __float2bfloat16_rn(o0 - __bfloat162float(h0));
        lo[row * D + tid + 256] = __float2bfloat16_rn(o1 - __bfloat162float(h1));
    }
}

// ---------------------------------------------------------------------------
// FUSED cycle-1 epilogue: relu+LN (warp-per-row) then logits.
// ---------------------------------------------------------------------------
__global__ void __launch_bounds__(256)
relu_ln_logits(const float* __restrict__ x, const float* __restrict__ w,
               const float* __restrict__ bb, const float* __restrict__ Wo,
               const float* __restrict__ bo, float* __restrict__ out) {
    __shared__ float Wsh[512 * T];
    __shared__ float wsh[512], bsh[512];
    int tid = threadIdx.x;
    for (int i = tid; i < 512 * T; i += 256) Wsh[i] = Wo[i];
    for (int i = tid; i < 512; i += 256) { wsh[i] = w[i]; bsh[i] = bb[i]; }
    __syncthreads();

    int warp = tid >> 5, lane = tid & 31;
    int row = blockIdx.x * 8 + warp;
    const float* xr = x + (size_t)row * D;

    float v[16];
    float sum = 0.f;
    #pragma unroll
    for (int j = 0; j < 16; j++) {
        v[j] = fmaxf(xr[lane + 32 * j], 0.f);
        sum += v[j];
    }
    #pragma unroll
    for (int o = 16; o > 0; o >>= 1) sum += __shfl_xor_sync(0xffffffffu, sum, o);
    float mean = sum * (1.f / 512.f);
    float var = 0.f;
    #pragma unroll
    for (int j = 0; j < 16; j++) {
        v[j] -= mean;
        var += v[j] * v[j];
    }
    #pragma unroll
    for (int o = 16; o > 0; o >>= 1) var += __shfl_xor_sync(0xffffffffu, var, o);
    float inv = rsqrtf(var * (1.f / 512.f) + 1e-12f);

    float acc[T];
    #pragma unroll
    for (int t = 0; t < T; t++) acc[t] = 0.f;
    #pragma unroll
    for (int j = 0; j < 16; j++) {
        int k = lane + 32 * j;
        float hk = wsh[k] * v[j] * inv + bsh[k];
        #pragma unroll
        for (int t = 0; t < T; t++) acc[t] = fmaf(hk, Wsh[k * T + t], acc[t]);
    }
    #pragma unroll
    for (int t = 0; t < T; t++)
        #pragma unroll
        for (int o = 16; o > 0; o >>= 1)
            acc[t] += __shfl_xor_sync(0xffffffffu, acc[t], o);
    if (lane == 0) {
        #pragma unroll
        for (int t = 0; t < T; t++) out[row * T + t] = acc[t] + bo[t];
    }
}

// ---------------------------------------------------------------------------
// Launch (two-stream overlap; s2 ALWAYS forked from stream 0 via event first)
// ---------------------------------------------------------------------------
extern "C" void kernel_launch(void* const* d_in, const int* in_sizes, int n_in,
                              void* d_out, int out_size) {
    (void)in_sizes; (void)n_in; (void)out_size;
    const int*   tokens  = (const int*)  d_in[0];
    const float* emb     = (const float*)d_in[4];
    Ptr8 wsrc = {{ (const float*)d_in[5],  (const float*)d_in[7],
                   (const float*)d_in[9],  (const float*)d_in[11],
                   (const float*)d_in[13], (const float*)d_in[15],
                   (const float*)d_in[17], (const float*)d_in[19] }};
    Ptr8 bsrc = {{ (const float*)d_in[6],  (const float*)d_in[8],
                   (const float*)d_in[10], (const float*)d_in[12],
                   (const float*)d_in[14], (const float*)d_in[16],
                   (const float*)d_in[18], (const float*)d_in[20] }};
    const float* sat_kw = (const float*)d_in[7];
    const float* sat_kb = (const float*)d_in[8];
    const float* sat_vw = (const float*)d_in[9];
    const float* sat_vb = (const float*)d_in[10];
    const float* rel_qw = (const float*)d_in[13];
    const float* rel_qb = (const float*)d_in[14];
    const float* rel_kw = (const float*)d_in[15];
    const float* rel_kb = (const float*)d_in[16];
    const float* rel_vw = (const float*)d_in[17];
    const float* rel_vb = (const float*)d_in[18];
    const float* rel_ow = (const float*)d_in[19];
    const float* rel_ob = (const float*)d_in[20];
    const float* ln_sw  = (const float*)d_in[21];
    const float* ln_sb  = (const float*)d_in[22];
    const float* ln_rw  = (const float*)d_in[23];
    const float* ln_rb  = (const float*)d_in[24];
    const float* ofc_w  = (const float*)d_in[25];
    const float* ofc_b  = (const float*)d_in[26];
    float* out = (float*)d_out;

    float *h, *s, *qkv, *qkeve, *krvr, *a;
    float *ks, *vs, *qsr, *ksr, *vsr, *ctxs, *r, *bias, *part;
    __nv_bfloat16 *ehi, *elo, *hhi, *hlo, *cthi, *ctlo, *whi, *wlo;
    cudaGetSymbolAddress((void**)&h,     g_h);
    cudaGetSymbolAddress((void**)&s,     g_s);
    cudaGetSymbolAddress((void**)&qkv,   g_qkv);
    cudaGetSymbolAddress((void**)&qkeve, g_qkeve);
    cudaGetSymbolAddress((void**)&krvr,  g_krvr);
    cudaGetSymbolAddress((void**)&a,     g_a);
    cudaGetSymbolAddress((void**)&ks,    g_ks);
    cudaGetSymbolAddress((void**)&vs,    g_vs);
    cudaGetSymbolAddress((void**)&qsr,   g_qsr);
    cudaGetSymbolAddress((void**)&ksr,   g_ksr);
    cudaGetSymbolAddress((void**)&vsr,   g_vsr);
    cudaGetSymbolAddress((void**)&ctxs,  g_ctxs);
    cudaGetSymbolAddress((void**)&r,     g_r);
    cudaGetSymbolAddress((void**)&bias,  g_bias);
    cudaGetSymbolAddress((void**)&part,  g_part);
    cudaGetSymbolAddress((void**)&ehi,   g_ehi);
    cudaGetSymbolAddress((void**)&elo,   g_elo);
    cudaGetSymbolAddress((void**)&hhi,   g_hhi);
    cudaGetSymbolAddress((void**)&hlo,   g_hlo);
    cudaGetSymbolAddress((void**)&cthi,  g_cthi);
    cudaGetSymbolAddress((void**)&ctlo,  g_ctlo);
    cudaGetSymbolAddress((void**)&whi,   g_whi);
    cudaGetSymbolAddress((void**)&wlo,   g_wlo);

    cudaFuncSetAttribute(mma_gemm, cudaFuncAttributeMaxDynamicSharedMemorySize,
                         SMEM_BYTES);

    cudaStream_t s2;
    cudaStreamCreateWithFlags(&s2, cudaStreamNonBlocking);
    cudaEvent_t ev0, evW, evA, evB, evC, evD;
    cudaEventCreateWithFlags(&ev0, cudaEventDisableTiming);
    cudaEventCreateWithFlags(&evW, cudaEventDisableTiming);
    cudaEventCreateWithFlags(&evA, cudaEventDisableTiming);
    cudaEventCreateWithFlags(&evB, cudaEventDisableTiming);
    cudaEventCreateWithFlags(&evC, cudaEventDisableTiming);
    cudaEventCreateWithFlags(&evD, cudaEventDisableTiming);

    #define GEMM(AHI, ALO, WI, NTOT, OUT, LDC, STRM)                           \
        mma_gemm<<<dim3((NTOT) / 128, 64), 256, SMEM_BYTES, STRM>>>(           \
            AHI, ALO, whi + (WI) * DD, wlo + (WI) * DD, bias + (WI) * 512,     \
            OUT, LDC)

    #define SMALL(AIN, JOBS, NJ, STRM)                                         \
        do {                                                                   \
            sgemm16_part<<<dim3(8, NJ), 256, 0, STRM>>>(AIN, JOBS, part);      \
            sgemm16_red<<<dim3(32, NJ), 256, 0, STRM>>>(JOBS, part);           \
        } while (0)

    // Legal fork: record on the capturing stream FIRST, then s2 waits.
    cudaEventRecord(ev0, 0);
    cudaStreamWaitEvent(s2, ev0, 0);

    // Prologue: weight prep (s2) ∥ embed (s0)
    wsplit_all<<<dim3(16, 16, 8), dim3(32, 8), 0, s2>>>(wsrc, whi, wlo);
    biascat<<<16, 256, 0, s2>>>(bsrc, bias);
    cudaEventRecord(evW, s2);
    embed_split<<<BL * D / 256, 256>>>(tokens, emb, ehi, elo);
    cudaEventRecord(evA, 0);

    // Stream 0: cycle-0 fused e-projection q | ke | ve (needs weights + embed)
    cudaStreamWaitEvent(0, evW, 0);
    GEMM(ehi, elo, 0, 1536, qkeve, 1536, 0);

    // Stream 2: smean + all 5 s-projections (needs embed)
    cudaStreamWaitEvent(s2, evA, 0);
    smean_kernel<<<B * 8, 256, 0, s2>>>(ehi, elo, s);
    {
        SJobs j = {{ sat_kw, sat_vw, rel_qw, rel_kw, rel_vw },
                   { sat_kb, sat_vb, rel_qb, rel_kb, rel_vb },
                   { ks, vs, qsr, ksr, vsr }};
        SMALL(s, j, 5, s2);
    }
    cudaEventRecord(evB, s2);
    cudaStreamWaitEvent(0, evB, 0);   // join before sat_attn

    // ---- cycle 0 (stream 0) ----
    sat_attn<<<BL, 256>>>(qkeve, 1536,
                          qkeve + 512, qkeve + 1024, 1536,
                          qkeve + 512, qkeve + 1024, 1536,
                          ks, vs, cthi, ctlo);
    GEMM(cthi, ctlo, 3, 512, a, 512, 0);           // sat_o
    relu_ln<<<BL, 256>>>(a, ln_sw, ln_sb, h, hhi, hlo);
    cudaEventRecord(evC, 0);

    // Stream 2: cycle-1 qkv GEMM (depends only on h split)
    cudaStreamWaitEvent(s2, evC, 0);
    GEMM(hhi, hlo, 0, 1536, qkv, 1536, s2);

    // Stream 0 (concurrent): rel chain
    GEMM(hhi, hlo, 5, 1024, krvr, 1024, 0);        // rel_k | rel_v
    rel_attn<<<B * NH, 256>>>(qsr, ksr, krvr, vsr, ctxs);
    {
        SJobs j = {{ rel_ow, nullptr, nullptr, nullptr, nullptr },
                   { rel_ob, nullptr, nullptr, nullptr, nullptr },
                   { r, nullptr, nullptr, nullptr, nullptr }};
        SMALL(ctxs, j, 1, 0);
    }
    relu_ln<<<B, 256>>>(r, ln_rw, ln_rb, s, nullptr, nullptr);
    {
        SJobs j = {{ sat_kw, sat_vw, nullptr, nullptr, nullptr },
                   { sat_kb, sat_vb, nullptr, nullptr, nullptr },
                   { ks, vs, nullptr, nullptr, nullptr }};
        SMALL(s, j, 2, 0);
    }
    cudaEventRecord(evD, s2);
    cudaStreamWaitEvent(0, evD, 0);   // join: sat_attn needs qkv

    // ---- cycle 1 (stream 0; rel path dead) ----
    sat_attn<<<BL, 256>>>(qkv, 1536,
                          qkv + 512, qkv + 1024, 1536,
                          qkeve + 512, qkeve + 1024, 1536,
                          ks, vs, cthi, ctlo);
    GEMM(cthi, ctlo, 3, 512, a, 512, 0);           // sat_o
    relu_ln_logits<<<BL / 8, 256>>>(a, ln_sw, ln_sb, ofc_w, ofc_b, out);

    cudaEventDestroy(ev0);
    cudaEventDestroy(evW);
    cudaEventDestroy(evA);
    cudaEventDestroy(evB);
    cudaEventDestroy(evC);
    cudaEventDestroy(evD);
    cudaStreamDestroy(s2);
}